// round 1
// baseline (speedup 1.0000x reference)
#include <cuda_runtime.h>
#include <math.h>

#define BATCH 4
#define SEQT 2048
#define CDIM 768
#define NHEAD 12
#define HDIM 64
#define MROWS (BATCH * SEQT)   // 8192

// Scratch (allocation-free rule: device globals)
__device__ float g_q[(size_t)MROWS * CDIM];
__device__ float g_k[(size_t)MROWS * CDIM];
__device__ float g_v[(size_t)MROWS * CDIM];
__device__ float g_att[(size_t)MROWS * CDIM];

// ---------------------------------------------------------------------------
// SGEMM: C[M,N] = A[M,K] @ W[K,N] + bias[N]
// 128x128 block tile, BK=8, 256 threads, 8x8 per thread.
// ---------------------------------------------------------------------------
__global__ __launch_bounds__(256, 2) void sgemm_bias(
    const float* __restrict__ A, const float* __restrict__ W,
    const float* __restrict__ bias, float* __restrict__ Cout,
    int Mdim, int Ndim, int Kdim)
{
    const int BM = 128, BN = 128, BK = 8;
    __shared__ float As[BK][BM];   // stored transposed: As[k][m]
    __shared__ float Bs[BK][BN];   // Bs[k][n]

    const int tid = threadIdx.x;
    const int tx = tid & 15;        // 0..15 -> N direction (8 cols each)
    const int ty = tid >> 4;        // 0..15 -> M direction (8 rows each)
    const int row0 = blockIdx.y * BM;
    const int col0 = blockIdx.x * BN;

    // load assignments
    const int a_row = tid >> 1;            // 0..127
    const int a_col = (tid & 1) << 2;      // 0 or 4
    const int b_row = tid >> 5;            // 0..7
    const int b_col = (tid & 31) << 2;     // 0..124

    const float* Ap = A + (size_t)(row0 + a_row) * Kdim + a_col;
    const float* Wp = W + (size_t)b_row * Ndim + col0 + b_col;

    float acc[8][8];
#pragma unroll
    for (int i = 0; i < 8; i++)
#pragma unroll
        for (int j = 0; j < 8; j++) acc[i][j] = 0.0f;

    for (int k0 = 0; k0 < Kdim; k0 += BK) {
        float4 av = *(const float4*)(Ap + k0);
        As[a_col + 0][a_row] = av.x;
        As[a_col + 1][a_row] = av.y;
        As[a_col + 2][a_row] = av.z;
        As[a_col + 3][a_row] = av.w;
        float4 bv = *(const float4*)(Wp + (size_t)k0 * Ndim);
        *(float4*)&Bs[b_row][b_col] = bv;
        __syncthreads();

#pragma unroll
        for (int k = 0; k < BK; k++) {
            float ar[8], br[8];
            *(float4*)&ar[0] = *(const float4*)&As[k][ty * 8];
            *(float4*)&ar[4] = *(const float4*)&As[k][ty * 8 + 4];
            *(float4*)&br[0] = *(const float4*)&Bs[k][tx * 8];
            *(float4*)&br[4] = *(const float4*)&Bs[k][tx * 8 + 4];
#pragma unroll
            for (int i = 0; i < 8; i++)
#pragma unroll
                for (int j = 0; j < 8; j++)
                    acc[i][j] = fmaf(ar[i], br[j], acc[i][j]);
        }
        __syncthreads();
    }

    // epilogue: + bias, vectorized stores
    float bvals[8];
    *(float4*)&bvals[0] = *(const float4*)&bias[col0 + tx * 8];
    *(float4*)&bvals[4] = *(const float4*)&bias[col0 + tx * 8 + 4];
#pragma unroll
    for (int i = 0; i < 8; i++) {
        const int r = row0 + ty * 8 + i;
        float* cp = Cout + (size_t)r * Ndim + col0 + tx * 8;
        float4 o0, o1;
        o0.x = acc[i][0] + bvals[0]; o0.y = acc[i][1] + bvals[1];
        o0.z = acc[i][2] + bvals[2]; o0.w = acc[i][3] + bvals[3];
        o1.x = acc[i][4] + bvals[4]; o1.y = acc[i][5] + bvals[5];
        o1.z = acc[i][6] + bvals[6]; o1.w = acc[i][7] + bvals[7];
        *(float4*)cp = o0;
        *(float4*)(cp + 4) = o1;
    }
}

// ---------------------------------------------------------------------------
// Flash attention (causal), fp32. Q/K/V in [B, T, C] with head slice h*64..
// BQ=128 query rows per block, K-tiles of 64. 256 threads, thread tile 8x4.
// Output written to g_att in [B, T, C] layout (already "transposed back").
// ---------------------------------------------------------------------------
#define BQ 128
#define BKT 64
#define PAD 65   // 65 % 32 == 1 -> bank = (row + col) % 32, max 2-way conflicts

__global__ __launch_bounds__(256, 2) void flash_attn(
    const float* __restrict__ Qg, const float* __restrict__ Kg,
    const float* __restrict__ Vg, float* __restrict__ Og)
{
    extern __shared__ float sm[];
    float* Qs = sm;                       // [BQ][PAD]
    float* Ks = Qs + BQ * PAD;            // [BKT][PAD]
    float* Vs = Ks + BKT * PAD;           // [BKT][PAD]
    float* Ps = Vs + BKT * PAD;           // [BQ][PAD]

    const int tid = threadIdx.x;
    const int tx = tid & 15;   // 4 cols of S / 4 d-cols of O
    const int ty = tid >> 4;   // 8 rows
    const int qi = blockIdx.x;
    const int h  = blockIdx.y;
    const int b  = blockIdx.z;
    const int qrow0 = qi * BQ;
    const float scale = 0.125f;  // 1/sqrt(64)

    // Load Q tile (pre-scaled)
    for (int it = tid; it < BQ * 16; it += 256) {
        const int r = it >> 4;
        const int quad = (it & 15) << 2;
        float4 v = *(const float4*)(Qg + (size_t)(b * SEQT + qrow0 + r) * CDIM + h * HDIM + quad);
        Qs[r * PAD + quad + 0] = v.x * scale;
        Qs[r * PAD + quad + 1] = v.y * scale;
        Qs[r * PAD + quad + 2] = v.z * scale;
        Qs[r * PAD + quad + 3] = v.w * scale;
    }

    float m[8], l[8], acc[8][4];
#pragma unroll
    for (int i = 0; i < 8; i++) {
        m[i] = -1e30f; l[i] = 0.0f;
#pragma unroll
        for (int j = 0; j < 4; j++) acc[i][j] = 0.0f;
    }

    const int nkt = 2 * qi + 2;  // k-tiles covering rows <= qrow0+127
    for (int kt = 0; kt < nkt; kt++) {
        __syncthreads();  // previous iteration finished with Ks/Vs/Ps
        // Load K,V tiles
        for (int it = tid; it < BKT * 16; it += 256) {
            const int r = it >> 4;
            const int quad = (it & 15) << 2;
            const size_t g = (size_t)(b * SEQT + kt * BKT + r) * CDIM + h * HDIM + quad;
            float4 kv = *(const float4*)(Kg + g);
            Ks[r * PAD + quad + 0] = kv.x;
            Ks[r * PAD + quad + 1] = kv.y;
            Ks[r * PAD + quad + 2] = kv.z;
            Ks[r * PAD + quad + 3] = kv.w;
            float4 vv = *(const float4*)(Vg + g);
            Vs[r * PAD + quad + 0] = vv.x;
            Vs[r * PAD + quad + 1] = vv.y;
            Vs[r * PAD + quad + 2] = vv.z;
            Vs[r * PAD + quad + 3] = vv.w;
        }
        __syncthreads();

        // S = Q @ K^T  (thread tile 8x4)
        float s[8][4];
#pragma unroll
        for (int i = 0; i < 8; i++)
#pragma unroll
            for (int j = 0; j < 4; j++) s[i][j] = 0.0f;

#pragma unroll 4
        for (int d = 0; d < HDIM; d++) {
            float ar[8], br[4];
#pragma unroll
            for (int ii = 0; ii < 8; ii++) ar[ii] = Qs[(ty * 8 + ii) * PAD + d];
#pragma unroll
            for (int jj = 0; jj < 4; jj++) br[jj] = Ks[(tx * 4 + jj) * PAD + d];
#pragma unroll
            for (int ii = 0; ii < 8; ii++)
#pragma unroll
                for (int jj = 0; jj < 4; jj++)
                    s[ii][jj] = fmaf(ar[ii], br[jj], s[ii][jj]);
        }

        // Causal mask (only tiles touching/above the diagonal)
        if (kt * BKT + BKT - 1 > qrow0) {
#pragma unroll
            for (int ii = 0; ii < 8; ii++) {
                const int qg = qrow0 + ty * 8 + ii;
#pragma unroll
                for (int jj = 0; jj < 4; jj++) {
                    const int kg = kt * BKT + tx * 4 + jj;
                    if (kg > qg) s[ii][jj] = -1e30f;
                }
            }
        }

        // Online softmax (row groups: 16 lanes share a row; xor-shfl over 1,2,4,8)
#pragma unroll
        for (int ii = 0; ii < 8; ii++) {
            float rm = s[ii][0];
            rm = fmaxf(rm, s[ii][1]);
            rm = fmaxf(rm, s[ii][2]);
            rm = fmaxf(rm, s[ii][3]);
            rm = fmaxf(rm, __shfl_xor_sync(0xffffffffu, rm, 8));
            rm = fmaxf(rm, __shfl_xor_sync(0xffffffffu, rm, 4));
            rm = fmaxf(rm, __shfl_xor_sync(0xffffffffu, rm, 2));
            rm = fmaxf(rm, __shfl_xor_sync(0xffffffffu, rm, 1));
            const float mn = fmaxf(m[ii], rm);
            const float f = __expf(m[ii] - mn);
            float rs = 0.0f;
#pragma unroll
            for (int jj = 0; jj < 4; jj++) {
                const float p = __expf(s[ii][jj] - mn);
                s[ii][jj] = p;
                rs += p;
            }
            rs += __shfl_xor_sync(0xffffffffu, rs, 8);
            rs += __shfl_xor_sync(0xffffffffu, rs, 4);
            rs += __shfl_xor_sync(0xffffffffu, rs, 2);
            rs += __shfl_xor_sync(0xffffffffu, rs, 1);
            l[ii] = l[ii] * f + rs;
            m[ii] = mn;
#pragma unroll
            for (int jj = 0; jj < 4; jj++) acc[ii][jj] *= f;
        }

        // Stage P to smem for the PV matmul
#pragma unroll
        for (int ii = 0; ii < 8; ii++)
#pragma unroll
            for (int jj = 0; jj < 4; jj++)
                Ps[(ty * 8 + ii) * PAD + tx * 4 + jj] = s[ii][jj];
        __syncthreads();

        // O += P @ V  (thread owns rows ty*8.., d-cols tx*4..)
#pragma unroll 4
        for (int j = 0; j < BKT; j++) {
            float vv[4];
#pragma unroll
            for (int jj = 0; jj < 4; jj++) vv[jj] = Vs[j * PAD + tx * 4 + jj];
#pragma unroll
            for (int ii = 0; ii < 8; ii++) {
                const float p = Ps[(ty * 8 + ii) * PAD + j];
#pragma unroll
                for (int jj = 0; jj < 4; jj++)
                    acc[ii][jj] = fmaf(p, vv[jj], acc[ii][jj]);
            }
        }
    }

    // Normalize and write in [B,T,C] layout
#pragma unroll
    for (int ii = 0; ii < 8; ii++) {
        const float inv = 1.0f / l[ii];
        const int r = qrow0 + ty * 8 + ii;
        float* op = Og + (size_t)(b * SEQT + r) * CDIM + h * HDIM + tx * 4;
        float4 o;
        o.x = acc[ii][0] * inv; o.y = acc[ii][1] * inv;
        o.z = acc[ii][2] * inv; o.w = acc[ii][3] * inv;
        *(float4*)op = o;
    }
}

// ---------------------------------------------------------------------------
// Launch
// ---------------------------------------------------------------------------
extern "C" void kernel_launch(void* const* d_in, const int* in_sizes, int n_in,
                              void* d_out, int out_size)
{
    (void)in_sizes; (void)n_in; (void)out_size;
    const float* x  = (const float*)d_in[0];
    const float* Wq = (const float*)d_in[1];
    const float* bq = (const float*)d_in[2];
    const float* Wk = (const float*)d_in[3];
    const float* bk = (const float*)d_in[4];
    const float* Wv = (const float*)d_in[5];
    const float* bv = (const float*)d_in[6];
    const float* Wo = (const float*)d_in[7];
    const float* bo = (const float*)d_in[8];
    float* out = (float*)d_out;

    float *q, *k, *v, *att;
    cudaGetSymbolAddress((void**)&q,   g_q);
    cudaGetSymbolAddress((void**)&k,   g_k);
    cudaGetSymbolAddress((void**)&v,   g_v);
    cudaGetSymbolAddress((void**)&att, g_att);

    const int smem_bytes = (BQ * PAD + BKT * PAD + BKT * PAD + BQ * PAD) * (int)sizeof(float);
    cudaFuncSetAttribute(flash_attn, cudaFuncAttributeMaxDynamicSharedMemorySize, smem_bytes);

    dim3 gemm_grid(CDIM / 128, MROWS / 128);   // (6, 64)
    sgemm_bias<<<gemm_grid, 256>>>(x, Wq, bq, q, MROWS, CDIM, CDIM);
    sgemm_bias<<<gemm_grid, 256>>>(x, Wk, bk, k, MROWS, CDIM, CDIM);
    sgemm_bias<<<gemm_grid, 256>>>(x, Wv, bv, v, MROWS, CDIM, CDIM);

    dim3 fa_grid(SEQT / BQ, NHEAD, BATCH);     // (16, 12, 4)
    flash_attn<<<fa_grid, 256, smem_bytes>>>(q, k, v, att);

    sgemm_bias<<<gemm_grid, 256>>>(att, Wo, bo, out, MROWS, CDIM, CDIM);
}

// round 3
// speedup vs baseline: 1.6187x; 1.6187x over previous
#include <cuda_runtime.h>
#include <cuda_bf16.h>
#include <math.h>
#include <stdint.h>

#define BATCH 4
#define SEQT 2048
#define CDIM 768
#define NHEAD 12
#define HDIM 64
#define MROWS (BATCH * SEQT)   // 8192

// ---------------------------------------------------------------------------
// Scratch (allocation-free rule: device globals)
// ---------------------------------------------------------------------------
__device__ float g_q[(size_t)MROWS * CDIM];
__device__ float g_k[(size_t)MROWS * CDIM];
__device__ float g_v[(size_t)MROWS * CDIM];
__device__ float g_att[(size_t)MROWS * CDIM];
__device__ __nv_bfloat16 g_xhi[(size_t)MROWS * CDIM];
__device__ __nv_bfloat16 g_xlo[(size_t)MROWS * CDIM];
__device__ __nv_bfloat16 g_ahi[(size_t)MROWS * CDIM];
__device__ __nv_bfloat16 g_alo[(size_t)MROWS * CDIM];
// transposed+split weights: [4][N=CDIM][K=CDIM]
__device__ __nv_bfloat16 g_wthi[4 * (size_t)CDIM * CDIM];
__device__ __nv_bfloat16 g_wtlo[4 * (size_t)CDIM * CDIM];

// ---------------------------------------------------------------------------
// PTX helpers (sm_80-era: legal under .target sm_103)
// ---------------------------------------------------------------------------
__device__ __forceinline__ uint32_t smem_to_u32(const void* p) {
    uint32_t a;
    asm("{ .reg .u64 t; cvta.to.shared.u64 t, %1; cvt.u32.u64 %0, t; }"
        : "=r"(a) : "l"(p));
    return a;
}

__device__ __forceinline__ void ldsm_x4(uint32_t* r, uint32_t addr) {
    asm volatile("ldmatrix.sync.aligned.m8n8.x4.shared.b16 {%0,%1,%2,%3}, [%4];"
        : "=r"(r[0]), "=r"(r[1]), "=r"(r[2]), "=r"(r[3]) : "r"(addr));
}

__device__ __forceinline__ void mma16816(float* c, const uint32_t* a, const uint32_t* b) {
    asm volatile(
        "mma.sync.aligned.m16n8k16.row.col.f32.bf16.bf16.f32 "
        "{%0,%1,%2,%3}, {%4,%5,%6,%7}, {%8,%9}, {%0,%1,%2,%3};"
        : "+f"(c[0]), "+f"(c[1]), "+f"(c[2]), "+f"(c[3])
        : "r"(a[0]), "r"(a[1]), "r"(a[2]), "r"(a[3]), "r"(b[0]), "r"(b[1]));
}

#define CP16(dst, src) \
    asm volatile("cp.async.cg.shared.global [%0], [%1], 16;" \
                 :: "r"(dst), "l"(src) : "memory")
#define CP_COMMIT() asm volatile("cp.async.commit_group;" ::: "memory")
#define CP_WAIT1()  asm volatile("cp.async.wait_group 1;" ::: "memory")
#define CP_WAIT0()  asm volatile("cp.async.wait_group 0;" ::: "memory")

#define SWZ128(off) ((off) ^ (((off) >> 3) & 0x70))

// ---------------------------------------------------------------------------
// Conversion kernels
// ---------------------------------------------------------------------------
__global__ void split_f32(const float* __restrict__ in,
                          __nv_bfloat16* __restrict__ hi,
                          __nv_bfloat16* __restrict__ lo, int n) {
    int i = blockIdx.x * blockDim.x + threadIdx.x;
    if (i < n) {
        float v = in[i];
        __nv_bfloat16 h = __float2bfloat16(v);
        float r = v - __bfloat162float(h);
        hi[i] = h;
        lo[i] = __float2bfloat16(r);
    }
}

// W[k][n] (fp32) -> Wt_hi/lo[n][k] (bf16), tiled transpose
__global__ void wtrans_split(const float* __restrict__ W,
                             __nv_bfloat16* __restrict__ hi,
                             __nv_bfloat16* __restrict__ lo) {
    __shared__ float t[32][33];
    const int kx = blockIdx.x * 32;
    const int nx = blockIdx.y * 32;
    const int tx = threadIdx.x, ty = threadIdx.y;
    for (int j = ty; j < 32; j += 8)
        t[j][tx] = W[(size_t)(kx + j) * CDIM + nx + tx];
    __syncthreads();
    for (int j = ty; j < 32; j += 8) {
        float v = t[tx][j];  // k = kx+tx, n = nx+j
        __nv_bfloat16 h = __float2bfloat16(v);
        float r = v - __bfloat162float(h);
        size_t o = (size_t)(nx + j) * CDIM + kx + tx;
        hi[o] = h;
        lo[o] = __float2bfloat16(r);
    }
}

// ---------------------------------------------------------------------------
// mma.sync split-bf16 GEMM: C[M,N] = A[M,K] @ W[K,N] + bias
//   Ahi/Alo: [M,K] bf16 row-major; Bhi/Blo: [N,K] bf16 row-major (W^T)
//   CTA tile 128x128, K-chunks of 64 (SW128 rows), cp.async double buffer.
//   8 warps: warp tile 32 (m) x 64 (n).
// ---------------------------------------------------------------------------
#define GK 64
#define NCHUNK (CDIM / GK)       // 12
#define BUF_BYTES 65536          // 4 tiles x 16KB
#define T_AHI 0
#define T_ALO 16384
#define T_BHI 32768
#define T_BLO 49152

__global__ __launch_bounds__(256, 1) void gemm_mma_split(
    const __nv_bfloat16* __restrict__ Ahi, const __nv_bfloat16* __restrict__ Alo,
    const __nv_bfloat16* __restrict__ Bhi, const __nv_bfloat16* __restrict__ Blo,
    const float* __restrict__ bias, float* __restrict__ Cout)
{
    extern __shared__ char smem[];
    const uint32_t sbase = smem_to_u32(smem);
    const int tid = threadIdx.x;
    const int lane = tid & 31;
    const int wid = tid >> 5;
    const int warp_m = wid >> 1;       // 0..3
    const int warp_n = wid & 1;        // 0..1
    const int col0 = blockIdx.x * 128;
    const int row0 = blockIdx.y * 128;

    // ldmatrix lane geometry
    const int lrow = lane & 7;
    const int lgrp = lane >> 3;
    const int a_roff = ((lgrp & 1) << 3) + lrow;   // row within 16-row tile
    const int a_kh   = (lgrp >> 1) << 4;           // k-half byte offset 0/16
    const int b_roff = ((lgrp >> 1) << 3) + lrow;
    const int b_kh   = (lgrp & 1) << 4;

    // load geometry: each thread moves 4 x 16B per tile per chunk
    const int ld_r   = tid >> 3;          // base row 0..31 (stride 32 over 4 iters)
    const int ld_c16 = (tid & 7) << 4;    // byte col within 128B row

    float acc[2][8][4];
#pragma unroll
    for (int i = 0; i < 2; i++)
#pragma unroll
        for (int j = 0; j < 8; j++)
#pragma unroll
            for (int r = 0; r < 4; r++) acc[i][j][r] = 0.0f;

    // ---- chunk loader (cp.async, swizzled) ----
    auto load_chunk = [&](int kc, int b) {
        const uint32_t sb = sbase + b * BUF_BYTES;
        const int kcol = kc * GK;
#pragma unroll
        for (int t = 0; t < 4; t++) {
            const int r = ld_r + t * 32;
            const uint32_t sw = SWZ128(r * 128 + ld_c16);
            const char* pa = (const char*)(Ahi + (size_t)(row0 + r) * CDIM + kcol) + ld_c16;
            const char* pal = (const char*)(Alo + (size_t)(row0 + r) * CDIM + kcol) + ld_c16;
            const char* pb = (const char*)(Bhi + (size_t)(col0 + r) * CDIM + kcol) + ld_c16;
            const char* pbl = (const char*)(Blo + (size_t)(col0 + r) * CDIM + kcol) + ld_c16;
            CP16(sb + T_AHI + sw, pa);
            CP16(sb + T_ALO + sw, pal);
            CP16(sb + T_BHI + sw, pb);
            CP16(sb + T_BLO + sw, pbl);
        }
    };

    load_chunk(0, 0);
    CP_COMMIT();

    for (int kc = 0; kc < NCHUNK; kc++) {
        const int cur = kc & 1;
        if (kc + 1 < NCHUNK) {
            load_chunk(kc + 1, cur ^ 1);
            CP_COMMIT();
            CP_WAIT1();
        } else {
            CP_WAIT0();
        }
        __syncthreads();

        const uint32_t sb = sbase + cur * BUF_BYTES;
#pragma unroll
        for (int s = 0; s < 4; s++) {
            const int kb = s * 32;
            uint32_t ahi[2][4], alo[2][4];
#pragma unroll
            for (int i = 0; i < 2; i++) {
                const uint32_t off =
                    SWZ128((warp_m * 32 + i * 16 + a_roff) * 128 + kb + a_kh);
                ldsm_x4(ahi[i], sb + T_AHI + off);
                ldsm_x4(alo[i], sb + T_ALO + off);
            }
            uint32_t bhi[8][2], blo[8][2];
#pragma unroll
            for (int j2 = 0; j2 < 4; j2++) {
                const uint32_t off =
                    SWZ128((warp_n * 64 + j2 * 16 + b_roff) * 128 + kb + b_kh);
                uint32_t t[4];
                ldsm_x4(t, sb + T_BHI + off);
                bhi[2 * j2][0] = t[0]; bhi[2 * j2][1] = t[1];
                bhi[2 * j2 + 1][0] = t[2]; bhi[2 * j2 + 1][1] = t[3];
                ldsm_x4(t, sb + T_BLO + off);
                blo[2 * j2][0] = t[0]; blo[2 * j2][1] = t[1];
                blo[2 * j2 + 1][0] = t[2]; blo[2 * j2 + 1][1] = t[3];
            }
            // hi@hi
#pragma unroll
            for (int i = 0; i < 2; i++)
#pragma unroll
                for (int j = 0; j < 8; j++)
                    mma16816(acc[i][j], ahi[i], bhi[j]);
            // hi@lo
#pragma unroll
            for (int i = 0; i < 2; i++)
#pragma unroll
                for (int j = 0; j < 8; j++)
                    mma16816(acc[i][j], ahi[i], blo[j]);
            // lo@hi
#pragma unroll
            for (int i = 0; i < 2; i++)
#pragma unroll
                for (int j = 0; j < 8; j++)
                    mma16816(acc[i][j], alo[i], bhi[j]);
        }
        __syncthreads();
    }

    // ---- epilogue: register fragments -> gmem (+bias) ----
#pragma unroll
    for (int i = 0; i < 2; i++) {
        const int mrow = row0 + warp_m * 32 + i * 16 + (lane >> 2);
#pragma unroll
        for (int j = 0; j < 8; j++) {
            const int ncol = col0 + warp_n * 64 + j * 8 + ((lane & 3) << 1);
            const float2 bv = *(const float2*)&bias[ncol];
            float2 o0, o1;
            o0.x = acc[i][j][0] + bv.x; o0.y = acc[i][j][1] + bv.y;
            o1.x = acc[i][j][2] + bv.x; o1.y = acc[i][j][3] + bv.y;
            *(float2*)&Cout[(size_t)mrow * CDIM + ncol] = o0;
            *(float2*)&Cout[(size_t)(mrow + 8) * CDIM + ncol] = o1;
        }
    }
}

// ---------------------------------------------------------------------------
// Flash attention (causal), fp32 — unchanged (Round 4 target)
// ---------------------------------------------------------------------------
#define BQ 128
#define BKT 64
#define PAD 65

__global__ __launch_bounds__(256, 2) void flash_attn(
    const float* __restrict__ Qg, const float* __restrict__ Kg,
    const float* __restrict__ Vg, float* __restrict__ Og)
{
    extern __shared__ float sm[];
    float* Qs = sm;
    float* Ks = Qs + BQ * PAD;
    float* Vs = Ks + BKT * PAD;
    float* Ps = Vs + BKT * PAD;

    const int tid = threadIdx.x;
    const int tx = tid & 15;
    const int ty = tid >> 4;
    const int qi = blockIdx.x;
    const int h  = blockIdx.y;
    const int b  = blockIdx.z;
    const int qrow0 = qi * BQ;
    const float scale = 0.125f;

    for (int it = tid; it < BQ * 16; it += 256) {
        const int r = it >> 4;
        const int quad = (it & 15) << 2;
        float4 v = *(const float4*)(Qg + (size_t)(b * SEQT + qrow0 + r) * CDIM + h * HDIM + quad);
        Qs[r * PAD + quad + 0] = v.x * scale;
        Qs[r * PAD + quad + 1] = v.y * scale;
        Qs[r * PAD + quad + 2] = v.z * scale;
        Qs[r * PAD + quad + 3] = v.w * scale;
    }

    float m[8], l[8], acc[8][4];
#pragma unroll
    for (int i = 0; i < 8; i++) {
        m[i] = -1e30f; l[i] = 0.0f;
#pragma unroll
        for (int j = 0; j < 4; j++) acc[i][j] = 0.0f;
    }

    const int nkt = 2 * qi + 2;
    for (int kt = 0; kt < nkt; kt++) {
        __syncthreads();
        for (int it = tid; it < BKT * 16; it += 256) {
            const int r = it >> 4;
            const int quad = (it & 15) << 2;
            const size_t g = (size_t)(b * SEQT + kt * BKT + r) * CDIM + h * HDIM + quad;
            float4 kv = *(const float4*)(Kg + g);
            Ks[r * PAD + quad + 0] = kv.x;
            Ks[r * PAD + quad + 1] = kv.y;
            Ks[r * PAD + quad + 2] = kv.z;
            Ks[r * PAD + quad + 3] = kv.w;
            float4 vv = *(const float4*)(Vg + g);
            Vs[r * PAD + quad + 0] = vv.x;
            Vs[r * PAD + quad + 1] = vv.y;
            Vs[r * PAD + quad + 2] = vv.z;
            Vs[r * PAD + quad + 3] = vv.w;
        }
        __syncthreads();

        float s[8][4];
#pragma unroll
        for (int i = 0; i < 8; i++)
#pragma unroll
            for (int j = 0; j < 4; j++) s[i][j] = 0.0f;

#pragma unroll 4
        for (int d = 0; d < HDIM; d++) {
            float ar[8], br[4];
#pragma unroll
            for (int ii = 0; ii < 8; ii++) ar[ii] = Qs[(ty * 8 + ii) * PAD + d];
#pragma unroll
            for (int jj = 0; jj < 4; jj++) br[jj] = Ks[(tx * 4 + jj) * PAD + d];
#pragma unroll
            for (int ii = 0; ii < 8; ii++)
#pragma unroll
                for (int jj = 0; jj < 4; jj++)
                    s[ii][jj] = fmaf(ar[ii], br[jj], s[ii][jj]);
        }

        if (kt * BKT + BKT - 1 > qrow0) {
#pragma unroll
            for (int ii = 0; ii < 8; ii++) {
                const int qg = qrow0 + ty * 8 + ii;
#pragma unroll
                for (int jj = 0; jj < 4; jj++) {
                    const int kg = kt * BKT + tx * 4 + jj;
                    if (kg > qg) s[ii][jj] = -1e30f;
                }
            }
        }

#pragma unroll
        for (int ii = 0; ii < 8; ii++) {
            float rm = s[ii][0];
            rm = fmaxf(rm, s[ii][1]);
            rm = fmaxf(rm, s[ii][2]);
            rm = fmaxf(rm, s[ii][3]);
            rm = fmaxf(rm, __shfl_xor_sync(0xffffffffu, rm, 8));
            rm = fmaxf(rm, __shfl_xor_sync(0xffffffffu, rm, 4));
            rm = fmaxf(rm, __shfl_xor_sync(0xffffffffu, rm, 2));
            rm = fmaxf(rm, __shfl_xor_sync(0xffffffffu, rm, 1));
            const float mn = fmaxf(m[ii], rm);
            const float f = __expf(m[ii] - mn);
            float rs = 0.0f;
#pragma unroll
            for (int jj = 0; jj < 4; jj++) {
                const float p = __expf(s[ii][jj] - mn);
                s[ii][jj] = p;
                rs += p;
            }
            rs += __shfl_xor_sync(0xffffffffu, rs, 8);
            rs += __shfl_xor_sync(0xffffffffu, rs, 4);
            rs += __shfl_xor_sync(0xffffffffu, rs, 2);
            rs += __shfl_xor_sync(0xffffffffu, rs, 1);
            l[ii] = l[ii] * f + rs;
            m[ii] = mn;
#pragma unroll
            for (int jj = 0; jj < 4; jj++) acc[ii][jj] *= f;
        }

#pragma unroll
        for (int ii = 0; ii < 8; ii++)
#pragma unroll
            for (int jj = 0; jj < 4; jj++)
                Ps[(ty * 8 + ii) * PAD + tx * 4 + jj] = s[ii][jj];
        __syncthreads();

#pragma unroll 4
        for (int j = 0; j < BKT; j++) {
            float vv[4];
#pragma unroll
            for (int jj = 0; jj < 4; jj++) vv[jj] = Vs[j * PAD + tx * 4 + jj];
#pragma unroll
            for (int ii = 0; ii < 8; ii++) {
                const float p = Ps[(ty * 8 + ii) * PAD + j];
#pragma unroll
                for (int jj = 0; jj < 4; jj++)
                    acc[ii][jj] = fmaf(p, vv[jj], acc[ii][jj]);
            }
        }
    }

#pragma unroll
    for (int ii = 0; ii < 8; ii++) {
        const float inv = 1.0f / l[ii];
        const int r = qrow0 + ty * 8 + ii;
        float* op = Og + (size_t)(b * SEQT + r) * CDIM + h * HDIM + tx * 4;
        float4 o;
        o.x = acc[ii][0] * inv; o.y = acc[ii][1] * inv;
        o.z = acc[ii][2] * inv; o.w = acc[ii][3] * inv;
        *(float4*)op = o;
    }
}

// ---------------------------------------------------------------------------
// Launch
// ---------------------------------------------------------------------------
extern "C" void kernel_launch(void* const* d_in, const int* in_sizes, int n_in,
                              void* d_out, int out_size)
{
    (void)in_sizes; (void)n_in; (void)out_size;
    const float* x  = (const float*)d_in[0];
    const float* Wq = (const float*)d_in[1];
    const float* bq = (const float*)d_in[2];
    const float* Wk = (const float*)d_in[3];
    const float* bk = (const float*)d_in[4];
    const float* Wv = (const float*)d_in[5];
    const float* bv = (const float*)d_in[6];
    const float* Wo = (const float*)d_in[7];
    const float* bo = (const float*)d_in[8];
    float* out = (float*)d_out;

    float *q, *k, *v, *att;
    __nv_bfloat16 *xhi, *xlo, *ahi, *alo, *wthi, *wtlo;
    cudaGetSymbolAddress((void**)&q,    g_q);
    cudaGetSymbolAddress((void**)&k,    g_k);
    cudaGetSymbolAddress((void**)&v,    g_v);
    cudaGetSymbolAddress((void**)&att,  g_att);
    cudaGetSymbolAddress((void**)&xhi,  g_xhi);
    cudaGetSymbolAddress((void**)&xlo,  g_xlo);
    cudaGetSymbolAddress((void**)&ahi,  g_ahi);
    cudaGetSymbolAddress((void**)&alo,  g_alo);
    cudaGetSymbolAddress((void**)&wthi, g_wthi);
    cudaGetSymbolAddress((void**)&wtlo, g_wtlo);

    const size_t WSZ = (size_t)CDIM * CDIM;

    const int gemm_smem = 2 * BUF_BYTES;   // 128KB double buffer
    cudaFuncSetAttribute(gemm_mma_split, cudaFuncAttributeMaxDynamicSharedMemorySize, gemm_smem);

    const int fa_smem = (BQ * PAD + BKT * PAD + BKT * PAD + BQ * PAD) * (int)sizeof(float);
    cudaFuncSetAttribute(flash_attn, cudaFuncAttributeMaxDynamicSharedMemorySize, fa_smem);

    const int nelem = MROWS * CDIM;

    // 1. split x -> bf16 hi/lo
    split_f32<<<(nelem + 255) / 256, 256>>>(x, xhi, xlo, nelem);

    // 2. transpose+split weights
    dim3 wt_grid(CDIM / 32, CDIM / 32);
    dim3 wt_blk(32, 8);
    wtrans_split<<<wt_grid, wt_blk>>>(Wq, wthi + 0 * WSZ, wtlo + 0 * WSZ);
    wtrans_split<<<wt_grid, wt_blk>>>(Wk, wthi + 1 * WSZ, wtlo + 1 * WSZ);
    wtrans_split<<<wt_grid, wt_blk>>>(Wv, wthi + 2 * WSZ, wtlo + 2 * WSZ);
    wtrans_split<<<wt_grid, wt_blk>>>(Wo, wthi + 3 * WSZ, wtlo + 3 * WSZ);

    // 3. QKV projections (mma.sync bf16 split)
    dim3 gemm_grid(CDIM / 128, MROWS / 128);   // (6, 64)
    gemm_mma_split<<<gemm_grid, 256, gemm_smem>>>(xhi, xlo, wthi + 0 * WSZ, wtlo + 0 * WSZ, bq, q);
    gemm_mma_split<<<gemm_grid, 256, gemm_smem>>>(xhi, xlo, wthi + 1 * WSZ, wtlo + 1 * WSZ, bk, k);
    gemm_mma_split<<<gemm_grid, 256, gemm_smem>>>(xhi, xlo, wthi + 2 * WSZ, wtlo + 2 * WSZ, bv, v);

    // 4. attention
    dim3 fa_grid(SEQT / BQ, NHEAD, BATCH);
    flash_attn<<<fa_grid, 256, fa_smem>>>(q, k, v, att);

    // 5. split attention output, 6. output projection
    split_f32<<<(nelem + 255) / 256, 256>>>(att, ahi, alo, nelem);
    gemm_mma_split<<<gemm_grid, 256, gemm_smem>>>(ahi, alo, wthi + 3 * WSZ, wtlo + 3 * WSZ, bo, out);
}

// round 4
// speedup vs baseline: 3.5018x; 2.1634x over previous
#include <cuda_runtime.h>
#include <cuda_bf16.h>
#include <math.h>
#include <stdint.h>

#define BATCH 4
#define SEQT 2048
#define CDIM 768
#define NHEAD 12
#define HDIM 64
#define MROWS (BATCH * SEQT)   // 8192

// ---------------------------------------------------------------------------
// Scratch (allocation-free rule: device globals)
// ---------------------------------------------------------------------------
__device__ __nv_bfloat16 g_xhi[(size_t)MROWS * CDIM];
__device__ __nv_bfloat16 g_xlo[(size_t)MROWS * CDIM];
__device__ __nv_bfloat16 g_qhi[(size_t)MROWS * CDIM];
__device__ __nv_bfloat16 g_qlo[(size_t)MROWS * CDIM];
__device__ __nv_bfloat16 g_khi[(size_t)MROWS * CDIM];
__device__ __nv_bfloat16 g_klo[(size_t)MROWS * CDIM];
__device__ __nv_bfloat16 g_vhi[(size_t)MROWS * CDIM];
__device__ __nv_bfloat16 g_vlo[(size_t)MROWS * CDIM];
__device__ __nv_bfloat16 g_ahi[(size_t)MROWS * CDIM];
__device__ __nv_bfloat16 g_alo[(size_t)MROWS * CDIM];
// transposed+split weights: [4][N=CDIM][K=CDIM]
__device__ __nv_bfloat16 g_wthi[4 * (size_t)CDIM * CDIM];
__device__ __nv_bfloat16 g_wtlo[4 * (size_t)CDIM * CDIM];

// ---------------------------------------------------------------------------
// PTX helpers (sm_80-era: legal under .target sm_103)
// ---------------------------------------------------------------------------
__device__ __forceinline__ uint32_t smem_to_u32(const void* p) {
    uint32_t a;
    asm("{ .reg .u64 t; cvta.to.shared.u64 t, %1; cvt.u32.u64 %0, t; }"
        : "=r"(a) : "l"(p));
    return a;
}

__device__ __forceinline__ void ldsm_x4(uint32_t* r, uint32_t addr) {
    asm volatile("ldmatrix.sync.aligned.m8n8.x4.shared.b16 {%0,%1,%2,%3}, [%4];"
        : "=r"(r[0]), "=r"(r[1]), "=r"(r[2]), "=r"(r[3]) : "r"(addr));
}

__device__ __forceinline__ void ldsm_x4_trans(uint32_t* r, uint32_t addr) {
    asm volatile("ldmatrix.sync.aligned.m8n8.x4.trans.shared.b16 {%0,%1,%2,%3}, [%4];"
        : "=r"(r[0]), "=r"(r[1]), "=r"(r[2]), "=r"(r[3]) : "r"(addr));
}

__device__ __forceinline__ void mma16816(float* c, const uint32_t* a, const uint32_t* b) {
    asm volatile(
        "mma.sync.aligned.m16n8k16.row.col.f32.bf16.bf16.f32 "
        "{%0,%1,%2,%3}, {%4,%5,%6,%7}, {%8,%9}, {%0,%1,%2,%3};"
        : "+f"(c[0]), "+f"(c[1]), "+f"(c[2]), "+f"(c[3])
        : "r"(a[0]), "r"(a[1]), "r"(a[2]), "r"(a[3]), "r"(b[0]), "r"(b[1]));
}

__device__ __forceinline__ float fast_ex2(float x) {
    float y;
    asm("ex2.approx.f32 %0, %1;" : "=f"(y) : "f"(x));
    return y;
}

#define CP16(dst, src) \
    asm volatile("cp.async.cg.shared.global [%0], [%1], 16;" \
                 :: "r"(dst), "l"(src) : "memory")
#define CP_COMMIT() asm volatile("cp.async.commit_group;" ::: "memory")
#define CP_WAIT1()  asm volatile("cp.async.wait_group 1;" ::: "memory")
#define CP_WAIT0()  asm volatile("cp.async.wait_group 0;" ::: "memory")

#define SWZ128(off) ((off) ^ (((off) >> 3) & 0x70))

// ---------------------------------------------------------------------------
// Conversion kernels
// ---------------------------------------------------------------------------
__global__ void split_f32(const float* __restrict__ in,
                          __nv_bfloat16* __restrict__ hi,
                          __nv_bfloat16* __restrict__ lo, int n) {
    int i = blockIdx.x * blockDim.x + threadIdx.x;
    if (i < n) {
        float v = in[i];
        __nv_bfloat16 h = __float2bfloat16(v);
        float r = v - __bfloat162float(h);
        hi[i] = h;
        lo[i] = __float2bfloat16(r);
    }
}

// W[k][n] (fp32) -> Wt_hi/lo[n][k] (bf16), tiled transpose
__global__ void wtrans_split(const float* __restrict__ W,
                             __nv_bfloat16* __restrict__ hi,
                             __nv_bfloat16* __restrict__ lo) {
    __shared__ float t[32][33];
    const int kx = blockIdx.x * 32;
    const int nx = blockIdx.y * 32;
    const int tx = threadIdx.x, ty = threadIdx.y;
    for (int j = ty; j < 32; j += 8)
        t[j][tx] = W[(size_t)(kx + j) * CDIM + nx + tx];
    __syncthreads();
    for (int j = ty; j < 32; j += 8) {
        float v = t[tx][j];  // k = kx+tx, n = nx+j
        __nv_bfloat16 h = __float2bfloat16(v);
        float r = v - __bfloat162float(h);
        size_t o = (size_t)(nx + j) * CDIM + kx + tx;
        hi[o] = h;
        lo[o] = __float2bfloat16(r);
    }
}

// ---------------------------------------------------------------------------
// mma.sync split-bf16 GEMM: C = A @ W + bias
//   SPLIT_OUT=true: write bf16 hi/lo (for q/k/v). false: write fp32.
// ---------------------------------------------------------------------------
#define GK 64
#define NCHUNK (CDIM / GK)       // 12
#define BUF_BYTES 65536
#define T_AHI 0
#define T_ALO 16384
#define T_BHI 32768
#define T_BLO 49152

template <bool SPLIT_OUT>
__global__ __launch_bounds__(256, 1) void gemm_mma_split(
    const __nv_bfloat16* __restrict__ Ahi, const __nv_bfloat16* __restrict__ Alo,
    const __nv_bfloat16* __restrict__ Bhi, const __nv_bfloat16* __restrict__ Blo,
    const float* __restrict__ bias, float* __restrict__ Cout,
    __nv_bfloat16* __restrict__ Chi, __nv_bfloat16* __restrict__ Clo)
{
    extern __shared__ char smem[];
    const uint32_t sbase = smem_to_u32(smem);
    const int tid = threadIdx.x;
    const int lane = tid & 31;
    const int wid = tid >> 5;
    const int warp_m = wid >> 1;
    const int warp_n = wid & 1;
    const int col0 = blockIdx.x * 128;
    const int row0 = blockIdx.y * 128;

    const int lrow = lane & 7;
    const int lgrp = lane >> 3;
    const int a_roff = ((lgrp & 1) << 3) + lrow;
    const int a_kh   = (lgrp >> 1) << 4;
    const int b_roff = ((lgrp >> 1) << 3) + lrow;
    const int b_kh   = (lgrp & 1) << 4;

    const int ld_r   = tid >> 3;
    const int ld_c16 = (tid & 7) << 4;

    float acc[2][8][4];
#pragma unroll
    for (int i = 0; i < 2; i++)
#pragma unroll
        for (int j = 0; j < 8; j++)
#pragma unroll
            for (int r = 0; r < 4; r++) acc[i][j][r] = 0.0f;

    auto load_chunk = [&](int kc, int bsel) {
        const uint32_t sb = sbase + bsel * BUF_BYTES;
        const int kcol = kc * GK;
#pragma unroll
        for (int t = 0; t < 4; t++) {
            const int r = ld_r + t * 32;
            const uint32_t sw = SWZ128(r * 128 + ld_c16);
            const char* pa = (const char*)(Ahi + (size_t)(row0 + r) * CDIM + kcol) + ld_c16;
            const char* pal = (const char*)(Alo + (size_t)(row0 + r) * CDIM + kcol) + ld_c16;
            const char* pb = (const char*)(Bhi + (size_t)(col0 + r) * CDIM + kcol) + ld_c16;
            const char* pbl = (const char*)(Blo + (size_t)(col0 + r) * CDIM + kcol) + ld_c16;
            CP16(sb + T_AHI + sw, pa);
            CP16(sb + T_ALO + sw, pal);
            CP16(sb + T_BHI + sw, pb);
            CP16(sb + T_BLO + sw, pbl);
        }
    };

    load_chunk(0, 0);
    CP_COMMIT();

    for (int kc = 0; kc < NCHUNK; kc++) {
        const int cur = kc & 1;
        if (kc + 1 < NCHUNK) {
            load_chunk(kc + 1, cur ^ 1);
            CP_COMMIT();
            CP_WAIT1();
        } else {
            CP_WAIT0();
        }
        __syncthreads();

        const uint32_t sb = sbase + cur * BUF_BYTES;
#pragma unroll
        for (int s = 0; s < 4; s++) {
            const int kb = s * 32;
            uint32_t ahi[2][4], alo[2][4];
#pragma unroll
            for (int i = 0; i < 2; i++) {
                const uint32_t off =
                    SWZ128((warp_m * 32 + i * 16 + a_roff) * 128 + kb + a_kh);
                ldsm_x4(ahi[i], sb + T_AHI + off);
                ldsm_x4(alo[i], sb + T_ALO + off);
            }
            uint32_t bhi[8][2], blo[8][2];
#pragma unroll
            for (int j2 = 0; j2 < 4; j2++) {
                const uint32_t off =
                    SWZ128((warp_n * 64 + j2 * 16 + b_roff) * 128 + kb + b_kh);
                uint32_t t[4];
                ldsm_x4(t, sb + T_BHI + off);
                bhi[2 * j2][0] = t[0]; bhi[2 * j2][1] = t[1];
                bhi[2 * j2 + 1][0] = t[2]; bhi[2 * j2 + 1][1] = t[3];
                ldsm_x4(t, sb + T_BLO + off);
                blo[2 * j2][0] = t[0]; blo[2 * j2][1] = t[1];
                blo[2 * j2 + 1][0] = t[2]; blo[2 * j2 + 1][1] = t[3];
            }
#pragma unroll
            for (int i = 0; i < 2; i++)
#pragma unroll
                for (int j = 0; j < 8; j++)
                    mma16816(acc[i][j], ahi[i], bhi[j]);
#pragma unroll
            for (int i = 0; i < 2; i++)
#pragma unroll
                for (int j = 0; j < 8; j++)
                    mma16816(acc[i][j], ahi[i], blo[j]);
#pragma unroll
            for (int i = 0; i < 2; i++)
#pragma unroll
                for (int j = 0; j < 8; j++)
                    mma16816(acc[i][j], alo[i], bhi[j]);
        }
        __syncthreads();
    }

    // ---- epilogue ----
#pragma unroll
    for (int i = 0; i < 2; i++) {
        const int mrow = row0 + warp_m * 32 + i * 16 + (lane >> 2);
#pragma unroll
        for (int j = 0; j < 8; j++) {
            const int ncol = col0 + warp_n * 64 + j * 8 + ((lane & 3) << 1);
            const float2 bv = *(const float2*)&bias[ncol];
            const float c0 = acc[i][j][0] + bv.x;
            const float c1 = acc[i][j][1] + bv.y;
            const float c2 = acc[i][j][2] + bv.x;
            const float c3 = acc[i][j][3] + bv.y;
            if (SPLIT_OUT) {
                __nv_bfloat162 h0 = __floats2bfloat162_rn(c0, c1);
                float2 hf0 = __bfloat1622float2(h0);
                __nv_bfloat162 l0 = __floats2bfloat162_rn(c0 - hf0.x, c1 - hf0.y);
                __nv_bfloat162 h1 = __floats2bfloat162_rn(c2, c3);
                float2 hf1 = __bfloat1622float2(h1);
                __nv_bfloat162 l1 = __floats2bfloat162_rn(c2 - hf1.x, c3 - hf1.y);
                *(__nv_bfloat162*)&Chi[(size_t)mrow * CDIM + ncol] = h0;
                *(__nv_bfloat162*)&Clo[(size_t)mrow * CDIM + ncol] = l0;
                *(__nv_bfloat162*)&Chi[(size_t)(mrow + 8) * CDIM + ncol] = h1;
                *(__nv_bfloat162*)&Clo[(size_t)(mrow + 8) * CDIM + ncol] = l1;
            } else {
                float2 o0, o1;
                o0.x = c0; o0.y = c1;
                o1.x = c2; o1.y = c3;
                *(float2*)&Cout[(size_t)mrow * CDIM + ncol] = o0;
                *(float2*)&Cout[(size_t)(mrow + 8) * CDIM + ncol] = o1;
            }
        }
    }
}

// ---------------------------------------------------------------------------
// Flash attention (causal) on mma.sync bf16 split.
//   BQ=128 (8 warps x 16 rows), BK=64. K/V double-buffered in smem.
//   Inputs bf16 hi/lo [B*T][C] head-sliced; output bf16 hi/lo.
// ---------------------------------------------------------------------------
#define S_QHI 0
#define S_QLO 16384
#define KV_BASE 32768
#define KV_BUF 32768
#define O_KHI 0
#define O_KLO 8192
#define O_VHI 16384
#define O_VLO 24576
#define FA_SMEM (KV_BASE + 2 * KV_BUF)   // 98304

__global__ __launch_bounds__(256, 1) void flash_attn_mma(
    const __nv_bfloat16* __restrict__ Qhi, const __nv_bfloat16* __restrict__ Qlo,
    const __nv_bfloat16* __restrict__ Khi, const __nv_bfloat16* __restrict__ Klo,
    const __nv_bfloat16* __restrict__ Vhi, const __nv_bfloat16* __restrict__ Vlo,
    __nv_bfloat16* __restrict__ Ohi, __nv_bfloat16* __restrict__ Olo)
{
    extern __shared__ char smem[];
    const uint32_t sbase = smem_to_u32(smem);
    const int tid = threadIdx.x;
    const int lane = tid & 31;
    const int wid = tid >> 5;
    const int qi = blockIdx.x;
    const int h = blockIdx.y;
    const int b = blockIdx.z;
    const int qrow0 = qi * 128;
    const int m0 = wid * 16;
    const int lr = lane & 7;
    const int lg = lane >> 3;
    const float CS = 0.125f * 1.44269504088896f;   // scale * log2(e)

    // ---- load Q tile (128 rows x 64 bf16, hi+lo), swizzled ----
#pragma unroll
    for (int t = 0; t < 4; t++) {
        const int idx = tid + t * 256;             // 0..1023
        const int r = idx >> 3;
        const int c16 = (idx & 7) << 4;
        const uint32_t sw = SWZ128(r * 128 + c16);
        const size_t grow = (size_t)(b * SEQT + qrow0 + r) * CDIM + h * HDIM;
        CP16(sbase + S_QHI + sw, (const char*)(Qhi + grow) + c16);
        CP16(sbase + S_QLO + sw, (const char*)(Qlo + grow) + c16);
    }
    CP_COMMIT();

    auto load_kv = [&](int kt, int bsel) {
        const uint32_t sb = sbase + KV_BASE + bsel * KV_BUF;
#pragma unroll
        for (int t = 0; t < 2; t++) {
            const int idx = tid + t * 256;         // 0..511
            const int r = idx >> 3;
            const int c16 = (idx & 7) << 4;
            const uint32_t sw = SWZ128(r * 128 + c16);
            const size_t grow = (size_t)(b * SEQT + kt * 64 + r) * CDIM + h * HDIM;
            CP16(sb + O_KHI + sw, (const char*)(Khi + grow) + c16);
            CP16(sb + O_KLO + sw, (const char*)(Klo + grow) + c16);
            CP16(sb + O_VHI + sw, (const char*)(Vhi + grow) + c16);
            CP16(sb + O_VLO + sw, (const char*)(Vlo + grow) + c16);
        }
        CP_COMMIT();
    };
    load_kv(0, 0);

    float o[8][4];
#pragma unroll
    for (int j = 0; j < 8; j++)
#pragma unroll
        for (int r = 0; r < 4; r++) o[j][r] = 0.0f;
    float mR[2] = {-1e30f, -1e30f};
    float lR[2] = {0.0f, 0.0f};

    const int nkt = 2 * qi + 2;
    for (int kt = 0; kt < nkt; kt++) {
        if (kt + 1 < nkt) {
            load_kv(kt + 1, (kt + 1) & 1);
            CP_WAIT1();
        } else {
            CP_WAIT0();
        }
        __syncthreads();
        const uint32_t kb = sbase + KV_BASE + (kt & 1) * KV_BUF;

        // ---- S = Q @ K^T (split bf16, 3 combos) ----
        float sacc[8][4];
#pragma unroll
        for (int j = 0; j < 8; j++)
#pragma unroll
            for (int r = 0; r < 4; r++) sacc[j][r] = 0.0f;

#pragma unroll
        for (int s = 0; s < 4; s++) {
            // Q fragments (A operand): row = m0 + (g&1)*8 + lr, col = s*32 + (g>>1)*16
            uint32_t qh[4], ql[4];
            {
                const uint32_t sw = SWZ128((m0 + ((lg & 1) << 3) + lr) * 128
                                           + s * 32 + ((lg >> 1) << 4));
                ldsm_x4(qh, sbase + S_QHI + sw);
                ldsm_x4(ql, sbase + S_QLO + sw);
            }
#pragma unroll
            for (int p = 0; p < 4; p++) {
                // K fragments (B operand): row = p*16 + (g>>1)*8 + lr, col = s*32 + (g&1)*16
                const uint32_t sw = SWZ128((p * 16 + ((lg >> 1) << 3) + lr) * 128
                                           + s * 32 + ((lg & 1) << 4));
                uint32_t kh[4], kl[4];
                ldsm_x4(kh, kb + O_KHI + sw);
                ldsm_x4(kl, kb + O_KLO + sw);
                mma16816(sacc[2 * p],     qh, &kh[0]);
                mma16816(sacc[2 * p + 1], qh, &kh[2]);
                mma16816(sacc[2 * p],     qh, &kl[0]);
                mma16816(sacc[2 * p + 1], qh, &kl[2]);
                mma16816(sacc[2 * p],     ql, &kh[0]);
                mma16816(sacc[2 * p + 1], ql, &kh[2]);
            }
        }

        // ---- causal mask ----
        if (kt * 64 + 63 > qrow0 + m0) {
            const int qg0 = qrow0 + m0 + (lane >> 2);
            const int qg1 = qg0 + 8;
#pragma unroll
            for (int j = 0; j < 8; j++) {
                const int kg = kt * 64 + j * 8 + ((lane & 3) << 1);
                if (kg > qg0)     sacc[j][0] = -1e30f;
                if (kg + 1 > qg0) sacc[j][1] = -1e30f;
                if (kg > qg1)     sacc[j][2] = -1e30f;
                if (kg + 1 > qg1) sacc[j][3] = -1e30f;
            }
        }

        // ---- online softmax (rows r0 = lane>>2, r1 = r0+8) ----
        float mp0 = sacc[0][0], mp1 = sacc[0][2];
#pragma unroll
        for (int j = 0; j < 8; j++) {
            mp0 = fmaxf(mp0, fmaxf(sacc[j][0], sacc[j][1]));
            mp1 = fmaxf(mp1, fmaxf(sacc[j][2], sacc[j][3]));
        }
        mp0 = fmaxf(mp0, __shfl_xor_sync(0xffffffffu, mp0, 1));
        mp0 = fmaxf(mp0, __shfl_xor_sync(0xffffffffu, mp0, 2));
        mp1 = fmaxf(mp1, __shfl_xor_sync(0xffffffffu, mp1, 1));
        mp1 = fmaxf(mp1, __shfl_xor_sync(0xffffffffu, mp1, 2));
        const float mn0 = fmaxf(mR[0], mp0);
        const float mn1 = fmaxf(mR[1], mp1);
        const float f0 = fast_ex2((mR[0] - mn0) * CS);
        const float f1 = fast_ex2((mR[1] - mn1) * CS);
        float sum0 = 0.0f, sum1 = 0.0f;
#pragma unroll
        for (int j = 0; j < 8; j++) {
            sacc[j][0] = fast_ex2((sacc[j][0] - mn0) * CS);
            sacc[j][1] = fast_ex2((sacc[j][1] - mn0) * CS);
            sacc[j][2] = fast_ex2((sacc[j][2] - mn1) * CS);
            sacc[j][3] = fast_ex2((sacc[j][3] - mn1) * CS);
            sum0 += sacc[j][0] + sacc[j][1];
            sum1 += sacc[j][2] + sacc[j][3];
        }
        sum0 += __shfl_xor_sync(0xffffffffu, sum0, 1);
        sum0 += __shfl_xor_sync(0xffffffffu, sum0, 2);
        sum1 += __shfl_xor_sync(0xffffffffu, sum1, 1);
        sum1 += __shfl_xor_sync(0xffffffffu, sum1, 2);
        lR[0] = lR[0] * f0 + sum0;
        lR[1] = lR[1] * f1 + sum1;
        mR[0] = mn0;
        mR[1] = mn1;
#pragma unroll
        for (int j = 0; j < 8; j++) {
            o[j][0] *= f0; o[j][1] *= f0;
            o[j][2] *= f1; o[j][3] *= f1;
        }

        // ---- O += P @ V (P split in registers, V split from smem) ----
#pragma unroll
        for (int s2 = 0; s2 < 4; s2++) {
            uint32_t ph[4], pl[4];
#pragma unroll
            for (int half = 0; half < 2; half++) {
                const int jt = 2 * s2 + half;
                __nv_bfloat162 h0 = __floats2bfloat162_rn(sacc[jt][0], sacc[jt][1]);
                float2 hf0 = __bfloat1622float2(h0);
                __nv_bfloat162 l0 =
                    __floats2bfloat162_rn(sacc[jt][0] - hf0.x, sacc[jt][1] - hf0.y);
                __nv_bfloat162 h1 = __floats2bfloat162_rn(sacc[jt][2], sacc[jt][3]);
                float2 hf1 = __bfloat1622float2(h1);
                __nv_bfloat162 l1 =
                    __floats2bfloat162_rn(sacc[jt][2] - hf1.x, sacc[jt][3] - hf1.y);
                ph[2 * half]     = *(uint32_t*)&h0;
                ph[2 * half + 1] = *(uint32_t*)&h1;
                pl[2 * half]     = *(uint32_t*)&l0;
                pl[2 * half + 1] = *(uint32_t*)&l1;
            }
#pragma unroll
            for (int dp = 0; dp < 4; dp++) {
                // V fragments (B, trans): row = s2*16 + (g&1)*8 + lr, col = dp*32 + (g>>1)*16
                const uint32_t sw = SWZ128((s2 * 16 + ((lg & 1) << 3) + lr) * 128
                                           + dp * 32 + ((lg >> 1) << 4));
                uint32_t vh[4], vl[4];
                ldsm_x4_trans(vh, kb + O_VHI + sw);
                ldsm_x4_trans(vl, kb + O_VLO + sw);
                mma16816(o[2 * dp],     ph, &vh[0]);
                mma16816(o[2 * dp + 1], ph, &vh[2]);
                mma16816(o[2 * dp],     ph, &vl[0]);
                mma16816(o[2 * dp + 1], ph, &vl[2]);
                mma16816(o[2 * dp],     pl, &vh[0]);
                mma16816(o[2 * dp + 1], pl, &vh[2]);
            }
        }
        __syncthreads();   // protect kv buffer before next prefetch overwrite
    }

    // ---- normalize + write bf16 hi/lo ----
    const float inv0 = 1.0f / lR[0];
    const float inv1 = 1.0f / lR[1];
    const int r0 = b * SEQT + qrow0 + m0 + (lane >> 2);
#pragma unroll
    for (int j = 0; j < 8; j++) {
        const int col = h * HDIM + j * 8 + ((lane & 3) << 1);
        const float c0 = o[j][0] * inv0, c1 = o[j][1] * inv0;
        const float c2 = o[j][2] * inv1, c3 = o[j][3] * inv1;
        __nv_bfloat162 h0 = __floats2bfloat162_rn(c0, c1);
        float2 hf0 = __bfloat1622float2(h0);
        __nv_bfloat162 l0 = __floats2bfloat162_rn(c0 - hf0.x, c1 - hf0.y);
        __nv_bfloat162 h1 = __floats2bfloat162_rn(c2, c3);
        float2 hf1 = __bfloat1622float2(h1);
        __nv_bfloat162 l1 = __floats2bfloat162_rn(c2 - hf1.x, c3 - hf1.y);
        *(__nv_bfloat162*)&Ohi[(size_t)r0 * CDIM + col] = h0;
        *(__nv_bfloat162*)&Olo[(size_t)r0 * CDIM + col] = l0;
        *(__nv_bfloat162*)&Ohi[(size_t)(r0 + 8) * CDIM + col] = h1;
        *(__nv_bfloat162*)&Olo[(size_t)(r0 + 8) * CDIM + col] = l1;
    }
}

// ---------------------------------------------------------------------------
// Launch
// ---------------------------------------------------------------------------
extern "C" void kernel_launch(void* const* d_in, const int* in_sizes, int n_in,
                              void* d_out, int out_size)
{
    (void)in_sizes; (void)n_in; (void)out_size;
    const float* x  = (const float*)d_in[0];
    const float* Wq = (const float*)d_in[1];
    const float* bq = (const float*)d_in[2];
    const float* Wk = (const float*)d_in[3];
    const float* bk = (const float*)d_in[4];
    const float* Wv = (const float*)d_in[5];
    const float* bv = (const float*)d_in[6];
    const float* Wo = (const float*)d_in[7];
    const float* bo = (const float*)d_in[8];
    float* out = (float*)d_out;

    __nv_bfloat16 *xhi, *xlo, *qhi, *qlo, *khi, *klo, *vhi, *vlo, *ahi, *alo, *wthi, *wtlo;
    cudaGetSymbolAddress((void**)&xhi,  g_xhi);
    cudaGetSymbolAddress((void**)&xlo,  g_xlo);
    cudaGetSymbolAddress((void**)&qhi,  g_qhi);
    cudaGetSymbolAddress((void**)&qlo,  g_qlo);
    cudaGetSymbolAddress((void**)&khi,  g_khi);
    cudaGetSymbolAddress((void**)&klo,  g_klo);
    cudaGetSymbolAddress((void**)&vhi,  g_vhi);
    cudaGetSymbolAddress((void**)&vlo,  g_vlo);
    cudaGetSymbolAddress((void**)&ahi,  g_ahi);
    cudaGetSymbolAddress((void**)&alo,  g_alo);
    cudaGetSymbolAddress((void**)&wthi, g_wthi);
    cudaGetSymbolAddress((void**)&wtlo, g_wtlo);

    const size_t WSZ = (size_t)CDIM * CDIM;

    const int gemm_smem = 2 * BUF_BYTES;
    cudaFuncSetAttribute(gemm_mma_split<true>,
                         cudaFuncAttributeMaxDynamicSharedMemorySize, gemm_smem);
    cudaFuncSetAttribute(gemm_mma_split<false>,
                         cudaFuncAttributeMaxDynamicSharedMemorySize, gemm_smem);
    cudaFuncSetAttribute(flash_attn_mma,
                         cudaFuncAttributeMaxDynamicSharedMemorySize, FA_SMEM);

    const int nelem = MROWS * CDIM;

    // 1. split x -> bf16 hi/lo
    split_f32<<<(nelem + 255) / 256, 256>>>(x, xhi, xlo, nelem);

    // 2. transpose+split weights
    dim3 wt_grid(CDIM / 32, CDIM / 32);
    dim3 wt_blk(32, 8);
    wtrans_split<<<wt_grid, wt_blk>>>(Wq, wthi + 0 * WSZ, wtlo + 0 * WSZ);
    wtrans_split<<<wt_grid, wt_blk>>>(Wk, wthi + 1 * WSZ, wtlo + 1 * WSZ);
    wtrans_split<<<wt_grid, wt_blk>>>(Wv, wthi + 2 * WSZ, wtlo + 2 * WSZ);
    wtrans_split<<<wt_grid, wt_blk>>>(Wo, wthi + 3 * WSZ, wtlo + 3 * WSZ);

    // 3. QKV projections -> bf16 hi/lo outputs directly
    dim3 gemm_grid(CDIM / 128, MROWS / 128);   // (6, 64)
    gemm_mma_split<true><<<gemm_grid, 256, gemm_smem>>>(
        xhi, xlo, wthi + 0 * WSZ, wtlo + 0 * WSZ, bq, nullptr, qhi, qlo);
    gemm_mma_split<true><<<gemm_grid, 256, gemm_smem>>>(
        xhi, xlo, wthi + 1 * WSZ, wtlo + 1 * WSZ, bk, nullptr, khi, klo);
    gemm_mma_split<true><<<gemm_grid, 256, gemm_smem>>>(
        xhi, xlo, wthi + 2 * WSZ, wtlo + 2 * WSZ, bv, nullptr, vhi, vlo);

    // 4. attention (tensor-core, split bf16) -> bf16 hi/lo
    dim3 fa_grid(SEQT / 128, NHEAD, BATCH);    // (16, 12, 4)
    flash_attn_mma<<<fa_grid, 256, FA_SMEM>>>(qhi, qlo, khi, klo, vhi, vlo, ahi, alo);

    // 5. output projection -> fp32 out
    gemm_mma_split<false><<<gemm_grid, 256, gemm_smem>>>(
        ahi, alo, wthi + 3 * WSZ, wtlo + 3 * WSZ, bo, out, nullptr, nullptr);
}

// round 5
// speedup vs baseline: 3.5708x; 1.0197x over previous
#include <cuda_runtime.h>
#include <cuda_bf16.h>
#include <math.h>
#include <stdint.h>

#define BATCH 4
#define SEQT 2048
#define CDIM 768
#define NHEAD 12
#define HDIM 64
#define MROWS (BATCH * SEQT)   // 8192

// ---------------------------------------------------------------------------
// Scratch (allocation-free rule: device globals)
// ---------------------------------------------------------------------------
__device__ __nv_bfloat16 g_xhi[(size_t)MROWS * CDIM];
__device__ __nv_bfloat16 g_xlo[(size_t)MROWS * CDIM];
__device__ __nv_bfloat16 g_qhi[(size_t)MROWS * CDIM];
__device__ __nv_bfloat16 g_qlo[(size_t)MROWS * CDIM];
__device__ __nv_bfloat16 g_khi[(size_t)MROWS * CDIM];
__device__ __nv_bfloat16 g_klo[(size_t)MROWS * CDIM];
__device__ __nv_bfloat16 g_vhi[(size_t)MROWS * CDIM];
__device__ __nv_bfloat16 g_vlo[(size_t)MROWS * CDIM];
__device__ __nv_bfloat16 g_ahi[(size_t)MROWS * CDIM];
__device__ __nv_bfloat16 g_alo[(size_t)MROWS * CDIM];
// transposed+split weights: [4][N=CDIM][K=CDIM]
__device__ __nv_bfloat16 g_wthi[4 * (size_t)CDIM * CDIM];
__device__ __nv_bfloat16 g_wtlo[4 * (size_t)CDIM * CDIM];

// ---------------------------------------------------------------------------
// PTX helpers (sm_80-era: legal under .target sm_103)
// ---------------------------------------------------------------------------
__device__ __forceinline__ uint32_t smem_to_u32(const void* p) {
    uint32_t a;
    asm("{ .reg .u64 t; cvta.to.shared.u64 t, %1; cvt.u32.u64 %0, t; }"
        : "=r"(a) : "l"(p));
    return a;
}

__device__ __forceinline__ void ldsm_x4(uint32_t* r, uint32_t addr) {
    asm volatile("ldmatrix.sync.aligned.m8n8.x4.shared.b16 {%0,%1,%2,%3}, [%4];"
        : "=r"(r[0]), "=r"(r[1]), "=r"(r[2]), "=r"(r[3]) : "r"(addr));
}

__device__ __forceinline__ void ldsm_x4_trans(uint32_t* r, uint32_t addr) {
    asm volatile("ldmatrix.sync.aligned.m8n8.x4.trans.shared.b16 {%0,%1,%2,%3}, [%4];"
        : "=r"(r[0]), "=r"(r[1]), "=r"(r[2]), "=r"(r[3]) : "r"(addr));
}

__device__ __forceinline__ void mma16816(float* c, const uint32_t* a, const uint32_t* b) {
    asm volatile(
        "mma.sync.aligned.m16n8k16.row.col.f32.bf16.bf16.f32 "
        "{%0,%1,%2,%3}, {%4,%5,%6,%7}, {%8,%9}, {%0,%1,%2,%3};"
        : "+f"(c[0]), "+f"(c[1]), "+f"(c[2]), "+f"(c[3])
        : "r"(a[0]), "r"(a[1]), "r"(a[2]), "r"(a[3]), "r"(b[0]), "r"(b[1]));
}

__device__ __forceinline__ float fast_ex2(float x) {
    float y;
    asm("ex2.approx.f32 %0, %1;" : "=f"(y) : "f"(x));
    return y;
}

#define CP16(dst, src) \
    asm volatile("cp.async.cg.shared.global [%0], [%1], 16;" \
                 :: "r"(dst), "l"(src) : "memory")
#define CP_COMMIT() asm volatile("cp.async.commit_group;" ::: "memory")
#define CP_WAIT1()  asm volatile("cp.async.wait_group 1;" ::: "memory")
#define CP_WAIT0()  asm volatile("cp.async.wait_group 0;" ::: "memory")

#define SWZ128(off) ((off) ^ (((off) >> 3) & 0x70))

// ---------------------------------------------------------------------------
// Conversion kernels
// ---------------------------------------------------------------------------
__global__ void split_f32(const float* __restrict__ in,
                          __nv_bfloat16* __restrict__ hi,
                          __nv_bfloat16* __restrict__ lo, int n) {
    int i = blockIdx.x * blockDim.x + threadIdx.x;
    if (i < n) {
        float v = in[i];
        __nv_bfloat16 h = __float2bfloat16(v);
        float r = v - __bfloat162float(h);
        hi[i] = h;
        lo[i] = __float2bfloat16(r);
    }
}

// 4 weights W[k][n] (fp32) -> Wt_hi/lo[z][n][k] (bf16), tiled transpose, one launch
__global__ void wtrans_split4(const float* __restrict__ W0, const float* __restrict__ W1,
                              const float* __restrict__ W2, const float* __restrict__ W3,
                              __nv_bfloat16* __restrict__ hi,
                              __nv_bfloat16* __restrict__ lo) {
    __shared__ float t[32][33];
    const int z = blockIdx.z;
    const float* W = (z == 0) ? W0 : (z == 1) ? W1 : (z == 2) ? W2 : W3;
    const size_t zoff = (size_t)z * CDIM * CDIM;
    const int kx = blockIdx.x * 32;
    const int nx = blockIdx.y * 32;
    const int tx = threadIdx.x, ty = threadIdx.y;
    for (int j = ty; j < 32; j += 8)
        t[j][tx] = W[(size_t)(kx + j) * CDIM + nx + tx];
    __syncthreads();
    for (int j = ty; j < 32; j += 8) {
        float v = t[tx][j];  // k = kx+tx, n = nx+j
        __nv_bfloat16 h = __float2bfloat16(v);
        float r = v - __bfloat162float(h);
        size_t o = zoff + (size_t)(nx + j) * CDIM + kx + tx;
        hi[o] = h;
        lo[o] = __float2bfloat16(r);
    }
}

// ---------------------------------------------------------------------------
// mma.sync split-bf16 GEMM: C = A @ W + bias  (3-stage cp.async pipeline)
//   SPLIT_OUT=true: write bf16 hi/lo (for q/k/v). false: write fp32.
// ---------------------------------------------------------------------------
#define GK 64
#define NCHUNK (CDIM / GK)       // 12
#define BUF_BYTES 65536
#define NSTAGE 3
#define GEMM_SMEM (NSTAGE * BUF_BYTES)   // 196608
#define T_AHI 0
#define T_ALO 16384
#define T_BHI 32768
#define T_BLO 49152

template <bool SPLIT_OUT>
__global__ __launch_bounds__(256, 1) void gemm_mma_split(
    const __nv_bfloat16* __restrict__ Ahi, const __nv_bfloat16* __restrict__ Alo,
    const __nv_bfloat16* __restrict__ Bhi, const __nv_bfloat16* __restrict__ Blo,
    const float* __restrict__ bias, float* __restrict__ Cout,
    __nv_bfloat16* __restrict__ Chi, __nv_bfloat16* __restrict__ Clo)
{
    extern __shared__ char smem[];
    const uint32_t sbase = smem_to_u32(smem);
    const int tid = threadIdx.x;
    const int lane = tid & 31;
    const int wid = tid >> 5;
    const int warp_m = wid >> 1;
    const int warp_n = wid & 1;
    const int col0 = blockIdx.x * 128;
    const int row0 = blockIdx.y * 128;

    const int lrow = lane & 7;
    const int lgrp = lane >> 3;
    const int a_roff = ((lgrp & 1) << 3) + lrow;
    const int a_kh   = (lgrp >> 1) << 4;
    const int b_roff = ((lgrp >> 1) << 3) + lrow;
    const int b_kh   = (lgrp & 1) << 4;

    const int ld_r   = tid >> 3;
    const int ld_c16 = (tid & 7) << 4;

    float acc[2][8][4];
#pragma unroll
    for (int i = 0; i < 2; i++)
#pragma unroll
        for (int j = 0; j < 8; j++)
#pragma unroll
            for (int r = 0; r < 4; r++) acc[i][j][r] = 0.0f;

    auto load_chunk = [&](int kc, int stage) {
        const uint32_t sb = sbase + stage * BUF_BYTES;
        const int kcol = kc * GK;
#pragma unroll
        for (int t = 0; t < 4; t++) {
            const int r = ld_r + t * 32;
            const uint32_t sw = SWZ128(r * 128 + ld_c16);
            const char* pa = (const char*)(Ahi + (size_t)(row0 + r) * CDIM + kcol) + ld_c16;
            const char* pal = (const char*)(Alo + (size_t)(row0 + r) * CDIM + kcol) + ld_c16;
            const char* pb = (const char*)(Bhi + (size_t)(col0 + r) * CDIM + kcol) + ld_c16;
            const char* pbl = (const char*)(Blo + (size_t)(col0 + r) * CDIM + kcol) + ld_c16;
            CP16(sb + T_AHI + sw, pa);
            CP16(sb + T_ALO + sw, pal);
            CP16(sb + T_BHI + sw, pb);
            CP16(sb + T_BLO + sw, pbl);
        }
        CP_COMMIT();
    };

    load_chunk(0, 0);
    load_chunk(1, 1);

    int stage = 0;
    for (int kc = 0; kc < NCHUNK; kc++) {
        if (kc == NCHUNK - 1) { CP_WAIT0(); } else { CP_WAIT1(); }
        __syncthreads();   // chunk kc landed; all warps done reading stage buffer from kc-1
        if (kc + 2 < NCHUNK) {
            int st2 = stage + 2; if (st2 >= NSTAGE) st2 -= NSTAGE;
            load_chunk(kc + 2, st2);
        }

        const uint32_t sb = sbase + stage * BUF_BYTES;
#pragma unroll
        for (int s = 0; s < 4; s++) {
            const int kb = s * 32;
            uint32_t ahi[2][4], alo[2][4];
#pragma unroll
            for (int i = 0; i < 2; i++) {
                const uint32_t off =
                    SWZ128((warp_m * 32 + i * 16 + a_roff) * 128 + kb + a_kh);
                ldsm_x4(ahi[i], sb + T_AHI + off);
                ldsm_x4(alo[i], sb + T_ALO + off);
            }
            uint32_t bhi[8][2], blo[8][2];
#pragma unroll
            for (int j2 = 0; j2 < 4; j2++) {
                const uint32_t off =
                    SWZ128((warp_n * 64 + j2 * 16 + b_roff) * 128 + kb + b_kh);
                uint32_t t[4];
                ldsm_x4(t, sb + T_BHI + off);
                bhi[2 * j2][0] = t[0]; bhi[2 * j2][1] = t[1];
                bhi[2 * j2 + 1][0] = t[2]; bhi[2 * j2 + 1][1] = t[3];
                ldsm_x4(t, sb + T_BLO + off);
                blo[2 * j2][0] = t[0]; blo[2 * j2][1] = t[1];
                blo[2 * j2 + 1][0] = t[2]; blo[2 * j2 + 1][1] = t[3];
            }
#pragma unroll
            for (int i = 0; i < 2; i++)
#pragma unroll
                for (int j = 0; j < 8; j++)
                    mma16816(acc[i][j], ahi[i], bhi[j]);
#pragma unroll
            for (int i = 0; i < 2; i++)
#pragma unroll
                for (int j = 0; j < 8; j++)
                    mma16816(acc[i][j], ahi[i], blo[j]);
#pragma unroll
            for (int i = 0; i < 2; i++)
#pragma unroll
                for (int j = 0; j < 8; j++)
                    mma16816(acc[i][j], alo[i], bhi[j]);
        }
        if (++stage == NSTAGE) stage = 0;
    }

    // ---- epilogue ----
#pragma unroll
    for (int i = 0; i < 2; i++) {
        const int mrow = row0 + warp_m * 32 + i * 16 + (lane >> 2);
#pragma unroll
        for (int j = 0; j < 8; j++) {
            const int ncol = col0 + warp_n * 64 + j * 8 + ((lane & 3) << 1);
            const float2 bv = *(const float2*)&bias[ncol];
            const float c0 = acc[i][j][0] + bv.x;
            const float c1 = acc[i][j][1] + bv.y;
            const float c2 = acc[i][j][2] + bv.x;
            const float c3 = acc[i][j][3] + bv.y;
            if (SPLIT_OUT) {
                __nv_bfloat162 h0 = __floats2bfloat162_rn(c0, c1);
                float2 hf0 = __bfloat1622float2(h0);
                __nv_bfloat162 l0 = __floats2bfloat162_rn(c0 - hf0.x, c1 - hf0.y);
                __nv_bfloat162 h1 = __floats2bfloat162_rn(c2, c3);
                float2 hf1 = __bfloat1622float2(h1);
                __nv_bfloat162 l1 = __floats2bfloat162_rn(c2 - hf1.x, c3 - hf1.y);
                *(__nv_bfloat162*)&Chi[(size_t)mrow * CDIM + ncol] = h0;
                *(__nv_bfloat162*)&Clo[(size_t)mrow * CDIM + ncol] = l0;
                *(__nv_bfloat162*)&Chi[(size_t)(mrow + 8) * CDIM + ncol] = h1;
                *(__nv_bfloat162*)&Clo[(size_t)(mrow + 8) * CDIM + ncol] = l1;
            } else {
                float2 o0, o1;
                o0.x = c0; o0.y = c1;
                o1.x = c2; o1.y = c3;
                *(float2*)&Cout[(size_t)mrow * CDIM + ncol] = o0;
                *(float2*)&Cout[(size_t)(mrow + 8) * CDIM + ncol] = o1;
            }
        }
    }
}

// ---------------------------------------------------------------------------
// Flash attention (causal) on mma.sync bf16 split.
//   BQ=128 (8 warps x 16 rows), BK=64. K/V double-buffered, 1 sync per k-tile.
//   Q fragments hoisted to registers. Heavy CTAs scheduled first.
// ---------------------------------------------------------------------------
#define S_QHI 0
#define S_QLO 16384
#define KV_BASE 32768
#define KV_BUF 32768
#define O_KHI 0
#define O_KLO 8192
#define O_VHI 16384
#define O_VLO 24576
#define FA_SMEM (KV_BASE + 2 * KV_BUF)   // 98304

__global__ __launch_bounds__(256, 1) void flash_attn_mma(
    const __nv_bfloat16* __restrict__ Qhi, const __nv_bfloat16* __restrict__ Qlo,
    const __nv_bfloat16* __restrict__ Khi, const __nv_bfloat16* __restrict__ Klo,
    const __nv_bfloat16* __restrict__ Vhi, const __nv_bfloat16* __restrict__ Vlo,
    __nv_bfloat16* __restrict__ Ohi, __nv_bfloat16* __restrict__ Olo)
{
    extern __shared__ char smem[];
    const uint32_t sbase = smem_to_u32(smem);
    const int tid = threadIdx.x;
    const int lane = tid & 31;
    const int wid = tid >> 5;
    const int qi = (gridDim.x - 1) - blockIdx.x;   // heavy CTAs first
    const int h = blockIdx.y;
    const int b = blockIdx.z;
    const int qrow0 = qi * 128;
    const int m0 = wid * 16;
    const int lr = lane & 7;
    const int lg = lane >> 3;
    const float CS = 0.125f * 1.44269504088896f;   // scale * log2(e)

    // ---- load Q tile (128 rows x 64 bf16, hi+lo), swizzled (group 0) ----
#pragma unroll
    for (int t = 0; t < 4; t++) {
        const int idx = tid + t * 256;             // 0..1023
        const int r = idx >> 3;
        const int c16 = (idx & 7) << 4;
        const uint32_t sw = SWZ128(r * 128 + c16);
        const size_t grow = (size_t)(b * SEQT + qrow0 + r) * CDIM + h * HDIM;
        CP16(sbase + S_QHI + sw, (const char*)(Qhi + grow) + c16);
        CP16(sbase + S_QLO + sw, (const char*)(Qlo + grow) + c16);
    }
    CP_COMMIT();

    auto load_kv = [&](int kt, int bsel) {
        const uint32_t sb = sbase + KV_BASE + bsel * KV_BUF;
#pragma unroll
        for (int t = 0; t < 2; t++) {
            const int idx = tid + t * 256;         // 0..511
            const int r = idx >> 3;
            const int c16 = (idx & 7) << 4;
            const uint32_t sw = SWZ128(r * 128 + c16);
            const size_t grow = (size_t)(b * SEQT + kt * 64 + r) * CDIM + h * HDIM;
            CP16(sb + O_KHI + sw, (const char*)(Khi + grow) + c16);
            CP16(sb + O_KLO + sw, (const char*)(Klo + grow) + c16);
            CP16(sb + O_VHI + sw, (const char*)(Vhi + grow) + c16);
            CP16(sb + O_VLO + sw, (const char*)(Vlo + grow) + c16);
        }
        CP_COMMIT();
    };
    load_kv(0, 0);

    // ---- Q ready (kv0 may still fly); hoist Q fragments to registers ----
    CP_WAIT1();
    __syncthreads();
    uint32_t qfh[4][4], qfl[4][4];
#pragma unroll
    for (int s = 0; s < 4; s++) {
        const uint32_t sw = SWZ128((m0 + ((lg & 1) << 3) + lr) * 128
                                   + s * 32 + ((lg >> 1) << 4));
        ldsm_x4(qfh[s], sbase + S_QHI + sw);
        ldsm_x4(qfl[s], sbase + S_QLO + sw);
    }

    float o[8][4];
#pragma unroll
    for (int j = 0; j < 8; j++)
#pragma unroll
        for (int r = 0; r < 4; r++) o[j][r] = 0.0f;
    float mR[2] = {-1e30f, -1e30f};
    float lR[2] = {0.0f, 0.0f};

    const int nkt = 2 * qi + 2;
    for (int kt = 0; kt < nkt; kt++) {
        CP_WAIT0();        // kv(kt) landed
        __syncthreads();   // and everyone is done reading the other buffer
        if (kt + 1 < nkt) load_kv(kt + 1, (kt + 1) & 1);
        const uint32_t kb = sbase + KV_BASE + (kt & 1) * KV_BUF;

        // ---- S = Q @ K^T (split bf16, 3 combos) ----
        float sacc[8][4];
#pragma unroll
        for (int j = 0; j < 8; j++)
#pragma unroll
            for (int r = 0; r < 4; r++) sacc[j][r] = 0.0f;

#pragma unroll
        for (int s = 0; s < 4; s++) {
#pragma unroll
            for (int p = 0; p < 4; p++) {
                const uint32_t sw = SWZ128((p * 16 + ((lg >> 1) << 3) + lr) * 128
                                           + s * 32 + ((lg & 1) << 4));
                uint32_t kh[4], kl[4];
                ldsm_x4(kh, kb + O_KHI + sw);
                ldsm_x4(kl, kb + O_KLO + sw);
                mma16816(sacc[2 * p],     qfh[s], &kh[0]);
                mma16816(sacc[2 * p + 1], qfh[s], &kh[2]);
                mma16816(sacc[2 * p],     qfh[s], &kl[0]);
                mma16816(sacc[2 * p + 1], qfh[s], &kl[2]);
                mma16816(sacc[2 * p],     qfl[s], &kh[0]);
                mma16816(sacc[2 * p + 1], qfl[s], &kh[2]);
            }
        }

        // ---- causal mask ----
        if (kt * 64 + 63 > qrow0 + m0) {
            const int qg0 = qrow0 + m0 + (lane >> 2);
            const int qg1 = qg0 + 8;
#pragma unroll
            for (int j = 0; j < 8; j++) {
                const int kg = kt * 64 + j * 8 + ((lane & 3) << 1);
                if (kg > qg0)     sacc[j][0] = -1e30f;
                if (kg + 1 > qg0) sacc[j][1] = -1e30f;
                if (kg > qg1)     sacc[j][2] = -1e30f;
                if (kg + 1 > qg1) sacc[j][3] = -1e30f;
            }
        }

        // ---- online softmax (rows r0 = lane>>2, r1 = r0+8) ----
        float mp0 = sacc[0][0], mp1 = sacc[0][2];
#pragma unroll
        for (int j = 0; j < 8; j++) {
            mp0 = fmaxf(mp0, fmaxf(sacc[j][0], sacc[j][1]));
            mp1 = fmaxf(mp1, fmaxf(sacc[j][2], sacc[j][3]));
        }
        mp0 = fmaxf(mp0, __shfl_xor_sync(0xffffffffu, mp0, 1));
        mp0 = fmaxf(mp0, __shfl_xor_sync(0xffffffffu, mp0, 2));
        mp1 = fmaxf(mp1, __shfl_xor_sync(0xffffffffu, mp1, 1));
        mp1 = fmaxf(mp1, __shfl_xor_sync(0xffffffffu, mp1, 2));
        const float mn0 = fmaxf(mR[0], mp0);
        const float mn1 = fmaxf(mR[1], mp1);
        const float f0 = fast_ex2((mR[0] - mn0) * CS);
        const float f1 = fast_ex2((mR[1] - mn1) * CS);
        float sum0 = 0.0f, sum1 = 0.0f;
#pragma unroll
        for (int j = 0; j < 8; j++) {
            sacc[j][0] = fast_ex2((sacc[j][0] - mn0) * CS);
            sacc[j][1] = fast_ex2((sacc[j][1] - mn0) * CS);
            sacc[j][2] = fast_ex2((sacc[j][2] - mn1) * CS);
            sacc[j][3] = fast_ex2((sacc[j][3] - mn1) * CS);
            sum0 += sacc[j][0] + sacc[j][1];
            sum1 += sacc[j][2] + sacc[j][3];
        }
        sum0 += __shfl_xor_sync(0xffffffffu, sum0, 1);
        sum0 += __shfl_xor_sync(0xffffffffu, sum0, 2);
        sum1 += __shfl_xor_sync(0xffffffffu, sum1, 1);
        sum1 += __shfl_xor_sync(0xffffffffu, sum1, 2);
        lR[0] = lR[0] * f0 + sum0;
        lR[1] = lR[1] * f1 + sum1;
        mR[0] = mn0;
        mR[1] = mn1;
#pragma unroll
        for (int j = 0; j < 8; j++) {
            o[j][0] *= f0; o[j][1] *= f0;
            o[j][2] *= f1; o[j][3] *= f1;
        }

        // ---- O += P @ V (P split in registers, V split from smem) ----
#pragma unroll
        for (int s2 = 0; s2 < 4; s2++) {
            uint32_t ph[4], pl[4];
#pragma unroll
            for (int half = 0; half < 2; half++) {
                const int jt = 2 * s2 + half;
                __nv_bfloat162 h0 = __floats2bfloat162_rn(sacc[jt][0], sacc[jt][1]);
                float2 hf0 = __bfloat1622float2(h0);
                __nv_bfloat162 l0 =
                    __floats2bfloat162_rn(sacc[jt][0] - hf0.x, sacc[jt][1] - hf0.y);
                __nv_bfloat162 h1 = __floats2bfloat162_rn(sacc[jt][2], sacc[jt][3]);
                float2 hf1 = __bfloat1622float2(h1);
                __nv_bfloat162 l1 =
                    __floats2bfloat162_rn(sacc[jt][2] - hf1.x, sacc[jt][3] - hf1.y);
                ph[2 * half]     = *(uint32_t*)&h0;
                ph[2 * half + 1] = *(uint32_t*)&h1;
                pl[2 * half]     = *(uint32_t*)&l0;
                pl[2 * half + 1] = *(uint32_t*)&l1;
            }
#pragma unroll
            for (int dp = 0; dp < 4; dp++) {
                const uint32_t sw = SWZ128((s2 * 16 + ((lg & 1) << 3) + lr) * 128
                                           + dp * 32 + ((lg >> 1) << 4));
                uint32_t vh[4], vl[4];
                ldsm_x4_trans(vh, kb + O_VHI + sw);
                ldsm_x4_trans(vl, kb + O_VLO + sw);
                mma16816(o[2 * dp],     ph, &vh[0]);
                mma16816(o[2 * dp + 1], ph, &vh[2]);
                mma16816(o[2 * dp],     ph, &vl[0]);
                mma16816(o[2 * dp + 1], ph, &vl[2]);
                mma16816(o[2 * dp],     pl, &vh[0]);
                mma16816(o[2 * dp + 1], pl, &vh[2]);
            }
        }
    }

    // ---- normalize + write bf16 hi/lo ----
    const float inv0 = 1.0f / lR[0];
    const float inv1 = 1.0f / lR[1];
    const int r0 = b * SEQT + qrow0 + m0 + (lane >> 2);
#pragma unroll
    for (int j = 0; j < 8; j++) {
        const int col = h * HDIM + j * 8 + ((lane & 3) << 1);
        const float c0 = o[j][0] * inv0, c1 = o[j][1] * inv0;
        const float c2 = o[j][2] * inv1, c3 = o[j][3] * inv1;
        __nv_bfloat162 h0 = __floats2bfloat162_rn(c0, c1);
        float2 hf0 = __bfloat1622float2(h0);
        __nv_bfloat162 l0 = __floats2bfloat162_rn(c0 - hf0.x, c1 - hf0.y);
        __nv_bfloat162 h1 = __floats2bfloat162_rn(c2, c3);
        float2 hf1 = __bfloat1622float2(h1);
        __nv_bfloat162 l1 = __floats2bfloat162_rn(c2 - hf1.x, c3 - hf1.y);
        *(__nv_bfloat162*)&Ohi[(size_t)r0 * CDIM + col] = h0;
        *(__nv_bfloat162*)&Olo[(size_t)r0 * CDIM + col] = l0;
        *(__nv_bfloat162*)&Ohi[(size_t)(r0 + 8) * CDIM + col] = h1;
        *(__nv_bfloat162*)&Olo[(size_t)(r0 + 8) * CDIM + col] = l1;
    }
}

// ---------------------------------------------------------------------------
// Launch
// ---------------------------------------------------------------------------
extern "C" void kernel_launch(void* const* d_in, const int* in_sizes, int n_in,
                              void* d_out, int out_size)
{
    (void)in_sizes; (void)n_in; (void)out_size;
    const float* x  = (const float*)d_in[0];
    const float* Wq = (const float*)d_in[1];
    const float* bq = (const float*)d_in[2];
    const float* Wk = (const float*)d_in[3];
    const float* bk = (const float*)d_in[4];
    const float* Wv = (const float*)d_in[5];
    const float* bv = (const float*)d_in[6];
    const float* Wo = (const float*)d_in[7];
    const float* bo = (const float*)d_in[8];
    float* out = (float*)d_out;

    __nv_bfloat16 *xhi, *xlo, *qhi, *qlo, *khi, *klo, *vhi, *vlo, *ahi, *alo, *wthi, *wtlo;
    cudaGetSymbolAddress((void**)&xhi,  g_xhi);
    cudaGetSymbolAddress((void**)&xlo,  g_xlo);
    cudaGetSymbolAddress((void**)&qhi,  g_qhi);
    cudaGetSymbolAddress((void**)&qlo,  g_qlo);
    cudaGetSymbolAddress((void**)&khi,  g_khi);
    cudaGetSymbolAddress((void**)&klo,  g_klo);
    cudaGetSymbolAddress((void**)&vhi,  g_vhi);
    cudaGetSymbolAddress((void**)&vlo,  g_vlo);
    cudaGetSymbolAddress((void**)&ahi,  g_ahi);
    cudaGetSymbolAddress((void**)&alo,  g_alo);
    cudaGetSymbolAddress((void**)&wthi, g_wthi);
    cudaGetSymbolAddress((void**)&wtlo, g_wtlo);

    const size_t WSZ = (size_t)CDIM * CDIM;

    cudaFuncSetAttribute(gemm_mma_split<true>,
                         cudaFuncAttributeMaxDynamicSharedMemorySize, GEMM_SMEM);
    cudaFuncSetAttribute(gemm_mma_split<false>,
                         cudaFuncAttributeMaxDynamicSharedMemorySize, GEMM_SMEM);
    cudaFuncSetAttribute(flash_attn_mma,
                         cudaFuncAttributeMaxDynamicSharedMemorySize, FA_SMEM);

    const int nelem = MROWS * CDIM;

    // 1. split x -> bf16 hi/lo
    split_f32<<<(nelem + 255) / 256, 256>>>(x, xhi, xlo, nelem);

    // 2. transpose+split all 4 weights in one launch
    dim3 wt_grid(CDIM / 32, CDIM / 32, 4);
    dim3 wt_blk(32, 8);
    wtrans_split4<<<wt_grid, wt_blk>>>(Wq, Wk, Wv, Wo, wthi, wtlo);

    // 3. QKV projections -> bf16 hi/lo outputs directly
    dim3 gemm_grid(CDIM / 128, MROWS / 128);   // (6, 64)
    gemm_mma_split<true><<<gemm_grid, 256, GEMM_SMEM>>>(
        xhi, xlo, wthi + 0 * WSZ, wtlo + 0 * WSZ, bq, nullptr, qhi, qlo);
    gemm_mma_split<true><<<gemm_grid, 256, GEMM_SMEM>>>(
        xhi, xlo, wthi + 1 * WSZ, wtlo + 1 * WSZ, bk, nullptr, khi, klo);
    gemm_mma_split<true><<<gemm_grid, 256, GEMM_SMEM>>>(
        xhi, xlo, wthi + 2 * WSZ, wtlo + 2 * WSZ, bv, nullptr, vhi, vlo);

    // 4. attention (tensor-core, split bf16) -> bf16 hi/lo
    dim3 fa_grid(SEQT / 128, NHEAD, BATCH);    // (16, 12, 4)
    flash_attn_mma<<<fa_grid, 256, FA_SMEM>>>(qhi, qlo, khi, klo, vhi, vlo, ahi, alo);

    // 5. output projection -> fp32 out
    gemm_mma_split<false><<<gemm_grid, 256, GEMM_SMEM>>>(
        ahi, alo, wthi + 3 * WSZ, wtlo + 3 * WSZ, bo, out, nullptr, nullptr);
}

// round 6
// speedup vs baseline: 3.9190x; 1.0975x over previous
#include <cuda_runtime.h>
#include <cuda_bf16.h>
#include <math.h>
#include <stdint.h>

#define BATCH 4
#define SEQT 2048
#define CDIM 768
#define NHEAD 12
#define HDIM 64
#define MROWS (BATCH * SEQT)   // 8192

// ---------------------------------------------------------------------------
// Scratch (allocation-free rule: device globals)
// ---------------------------------------------------------------------------
__device__ __nv_bfloat16 g_xhi[(size_t)MROWS * CDIM];
__device__ __nv_bfloat16 g_xlo[(size_t)MROWS * CDIM];
__device__ __nv_bfloat16 g_qhi[(size_t)MROWS * CDIM];
__device__ __nv_bfloat16 g_qlo[(size_t)MROWS * CDIM];
__device__ __nv_bfloat16 g_khi[(size_t)MROWS * CDIM];
__device__ __nv_bfloat16 g_klo[(size_t)MROWS * CDIM];
__device__ __nv_bfloat16 g_vhi[(size_t)MROWS * CDIM];
__device__ __nv_bfloat16 g_vlo[(size_t)MROWS * CDIM];
__device__ __nv_bfloat16 g_ahi[(size_t)MROWS * CDIM];
__device__ __nv_bfloat16 g_alo[(size_t)MROWS * CDIM];
// transposed+split weights: [4][N=CDIM][K=CDIM] (order: Wq, Wk, Wv, Wo)
__device__ __nv_bfloat16 g_wthi[4 * (size_t)CDIM * CDIM];
__device__ __nv_bfloat16 g_wtlo[4 * (size_t)CDIM * CDIM];

// ---------------------------------------------------------------------------
// PTX helpers (sm_80-era: legal under .target sm_103)
// ---------------------------------------------------------------------------
__device__ __forceinline__ uint32_t smem_to_u32(const void* p) {
    uint32_t a;
    asm("{ .reg .u64 t; cvta.to.shared.u64 t, %1; cvt.u32.u64 %0, t; }"
        : "=r"(a) : "l"(p));
    return a;
}

__device__ __forceinline__ void ldsm_x4(uint32_t* r, uint32_t addr) {
    asm volatile("ldmatrix.sync.aligned.m8n8.x4.shared.b16 {%0,%1,%2,%3}, [%4];"
        : "=r"(r[0]), "=r"(r[1]), "=r"(r[2]), "=r"(r[3]) : "r"(addr));
}

__device__ __forceinline__ void ldsm_x4_trans(uint32_t* r, uint32_t addr) {
    asm volatile("ldmatrix.sync.aligned.m8n8.x4.trans.shared.b16 {%0,%1,%2,%3}, [%4];"
        : "=r"(r[0]), "=r"(r[1]), "=r"(r[2]), "=r"(r[3]) : "r"(addr));
}

__device__ __forceinline__ void mma16816(float* c, const uint32_t* a, const uint32_t* b) {
    asm volatile(
        "mma.sync.aligned.m16n8k16.row.col.f32.bf16.bf16.f32 "
        "{%0,%1,%2,%3}, {%4,%5,%6,%7}, {%8,%9}, {%0,%1,%2,%3};"
        : "+f"(c[0]), "+f"(c[1]), "+f"(c[2]), "+f"(c[3])
        : "r"(a[0]), "r"(a[1]), "r"(a[2]), "r"(a[3]), "r"(b[0]), "r"(b[1]));
}

__device__ __forceinline__ float fast_ex2(float x) {
    float y;
    asm("ex2.approx.f32 %0, %1;" : "=f"(y) : "f"(x));
    return y;
}

#define CP16(dst, src) \
    asm volatile("cp.async.cg.shared.global [%0], [%1], 16;" \
                 :: "r"(dst), "l"(src) : "memory")
#define CP_COMMIT() asm volatile("cp.async.commit_group;" ::: "memory")
#define CP_WAIT2()  asm volatile("cp.async.wait_group 2;" ::: "memory")
#define CP_WAIT1()  asm volatile("cp.async.wait_group 1;" ::: "memory")
#define CP_WAIT0()  asm volatile("cp.async.wait_group 0;" ::: "memory")

#define SWZ128(off) ((off) ^ (((off) >> 3) & 0x70))

// ---------------------------------------------------------------------------
// Conversion kernels
// ---------------------------------------------------------------------------
__global__ void split_f32(const float* __restrict__ in,
                          __nv_bfloat16* __restrict__ hi,
                          __nv_bfloat16* __restrict__ lo, int n) {
    int i = blockIdx.x * blockDim.x + threadIdx.x;
    if (i < n) {
        float v = in[i];
        __nv_bfloat16 h = __float2bfloat16(v);
        float r = v - __bfloat162float(h);
        hi[i] = h;
        lo[i] = __float2bfloat16(r);
    }
}

// 4 weights W[k][n] (fp32) -> Wt_hi/lo[z][n][k] (bf16), tiled transpose, one launch
__global__ void wtrans_split4(const float* __restrict__ W0, const float* __restrict__ W1,
                              const float* __restrict__ W2, const float* __restrict__ W3,
                              __nv_bfloat16* __restrict__ hi,
                              __nv_bfloat16* __restrict__ lo) {
    __shared__ float t[32][33];
    const int z = blockIdx.z;
    const float* W = (z == 0) ? W0 : (z == 1) ? W1 : (z == 2) ? W2 : W3;
    const size_t zoff = (size_t)z * CDIM * CDIM;
    const int kx = blockIdx.x * 32;
    const int nx = blockIdx.y * 32;
    const int tx = threadIdx.x, ty = threadIdx.y;
    for (int j = ty; j < 32; j += 8)
        t[j][tx] = W[(size_t)(kx + j) * CDIM + nx + tx];
    __syncthreads();
    for (int j = ty; j < 32; j += 8) {
        float v = t[tx][j];
        __nv_bfloat16 h = __float2bfloat16(v);
        float r = v - __bfloat162float(h);
        size_t o = zoff + (size_t)(nx + j) * CDIM + kx + tx;
        hi[o] = h;
        lo[o] = __float2bfloat16(r);
    }
}

// ---------------------------------------------------------------------------
// mma.sync split-bf16 GEMM, 128x64 tile, 48KB/chunk, 2 stages, 2 CTAs/SM.
//   SPLIT_OUT=true: fused QKV (grid.x = 36: wsel = x/12), bf16 hi/lo outputs.
//   SPLIT_OUT=false: Wo (grid.x = 12), fp32 output.
// ---------------------------------------------------------------------------
#define GK 64
#define NCHUNK (CDIM / GK)        // 12
#define CH_BYTES 49152            // A 32KB + B 16KB
#define GEMM_SMEM (2 * CH_BYTES)  // 98304
#define T_AHI 0
#define T_ALO 16384
#define T_BHI 32768
#define T_BLO 40960

template <bool SPLIT_OUT>
__global__ __launch_bounds__(256, 2) void gemm_mma_split(
    const __nv_bfloat16* __restrict__ Ahi, const __nv_bfloat16* __restrict__ Alo,
    const __nv_bfloat16* __restrict__ Wthi, const __nv_bfloat16* __restrict__ Wtlo,
    const float* __restrict__ b0, const float* __restrict__ b1,
    const float* __restrict__ b2,
    float* __restrict__ Cout,
    __nv_bfloat16* __restrict__ C0hi, __nv_bfloat16* __restrict__ C0lo,
    __nv_bfloat16* __restrict__ C1hi, __nv_bfloat16* __restrict__ C1lo,
    __nv_bfloat16* __restrict__ C2hi, __nv_bfloat16* __restrict__ C2lo)
{
    extern __shared__ char smem[];
    const uint32_t sbase = smem_to_u32(smem);
    const int tid = threadIdx.x;
    const int lane = tid & 31;
    const int wid = tid >> 5;
    const int warp_m = wid >> 1;       // 0..3
    const int warp_n = wid & 1;        // 0..1
    const int row0 = blockIdx.y * 128;

    int wsel, col0;
    if (SPLIT_OUT) { wsel = blockIdx.x / 12; col0 = (blockIdx.x % 12) * 64; }
    else           { wsel = 3;              col0 = blockIdx.x * 64; }

    const size_t WSZ = (size_t)CDIM * CDIM;
    const __nv_bfloat16* Bhi = Wthi + (size_t)wsel * WSZ;
    const __nv_bfloat16* Blo = Wtlo + (size_t)wsel * WSZ;
    const float* bias = SPLIT_OUT ? (wsel == 0 ? b0 : wsel == 1 ? b1 : b2) : b0;
    __nv_bfloat16* Chi = SPLIT_OUT ? (wsel == 0 ? C0hi : wsel == 1 ? C1hi : C2hi) : nullptr;
    __nv_bfloat16* Clo = SPLIT_OUT ? (wsel == 0 ? C0lo : wsel == 1 ? C1lo : C2lo) : nullptr;

    const int lrow = lane & 7;
    const int lgrp = lane >> 3;
    const int a_roff = ((lgrp & 1) << 3) + lrow;
    const int a_kh   = (lgrp >> 1) << 4;
    const int b_roff = ((lgrp >> 1) << 3) + lrow;
    const int b_kh   = (lgrp & 1) << 4;

    const int ld_r   = tid >> 3;
    const int ld_c16 = (tid & 7) << 4;

    float acc[2][4][4];
#pragma unroll
    for (int i = 0; i < 2; i++)
#pragma unroll
        for (int j = 0; j < 4; j++)
#pragma unroll
            for (int r = 0; r < 4; r++) acc[i][j][r] = 0.0f;

    auto load_chunk = [&](int kc, int stage) {
        const uint32_t sb = sbase + stage * CH_BYTES;
        const int kcol = kc * GK;
#pragma unroll
        for (int t = 0; t < 4; t++) {   // A: 128 rows, hi+lo
            const int r = ld_r + t * 32;
            const uint32_t sw = SWZ128(r * 128 + ld_c16);
            const char* pa  = (const char*)(Ahi + (size_t)(row0 + r) * CDIM + kcol) + ld_c16;
            const char* pal = (const char*)(Alo + (size_t)(row0 + r) * CDIM + kcol) + ld_c16;
            CP16(sb + T_AHI + sw, pa);
            CP16(sb + T_ALO + sw, pal);
        }
#pragma unroll
        for (int t = 0; t < 2; t++) {   // B: 64 rows, hi+lo
            const int idx = tid + t * 256;
            const int r = idx >> 3;
            const int c16 = (idx & 7) << 4;
            const uint32_t sw = SWZ128(r * 128 + c16);
            const char* pb  = (const char*)(Bhi + (size_t)(col0 + r) * CDIM + kcol) + c16;
            const char* pbl = (const char*)(Blo + (size_t)(col0 + r) * CDIM + kcol) + c16;
            CP16(sb + T_BHI + sw, pb);
            CP16(sb + T_BLO + sw, pbl);
        }
        CP_COMMIT();
    };

    load_chunk(0, 0);

    for (int kc = 0; kc < NCHUNK; kc++) {
        CP_WAIT0();        // chunk kc landed (issued last iteration or preloop)
        __syncthreads();   // all warps done computing kc-1 -> other buffer free
        if (kc + 1 < NCHUNK) load_chunk(kc + 1, (kc + 1) & 1);

        const uint32_t sb = sbase + (kc & 1) * CH_BYTES;
#pragma unroll
        for (int s = 0; s < 4; s++) {
            const int kb = s * 32;
            uint32_t ahi[2][4], alo[2][4];
#pragma unroll
            for (int i = 0; i < 2; i++) {
                const uint32_t off =
                    SWZ128((warp_m * 32 + i * 16 + a_roff) * 128 + kb + a_kh);
                ldsm_x4(ahi[i], sb + T_AHI + off);
                ldsm_x4(alo[i], sb + T_ALO + off);
            }
            uint32_t bhi[4][2], blo[4][2];
#pragma unroll
            for (int j2 = 0; j2 < 2; j2++) {
                const uint32_t off =
                    SWZ128((warp_n * 32 + j2 * 16 + b_roff) * 128 + kb + b_kh);
                uint32_t t[4];
                ldsm_x4(t, sb + T_BHI + off);
                bhi[2 * j2][0] = t[0]; bhi[2 * j2][1] = t[1];
                bhi[2 * j2 + 1][0] = t[2]; bhi[2 * j2 + 1][1] = t[3];
                ldsm_x4(t, sb + T_BLO + off);
                blo[2 * j2][0] = t[0]; blo[2 * j2][1] = t[1];
                blo[2 * j2 + 1][0] = t[2]; blo[2 * j2 + 1][1] = t[3];
            }
#pragma unroll
            for (int i = 0; i < 2; i++)
#pragma unroll
                for (int j = 0; j < 4; j++)
                    mma16816(acc[i][j], ahi[i], bhi[j]);
#pragma unroll
            for (int i = 0; i < 2; i++)
#pragma unroll
                for (int j = 0; j < 4; j++)
                    mma16816(acc[i][j], ahi[i], blo[j]);
#pragma unroll
            for (int i = 0; i < 2; i++)
#pragma unroll
                for (int j = 0; j < 4; j++)
                    mma16816(acc[i][j], alo[i], bhi[j]);
        }
    }

    // ---- epilogue ----
#pragma unroll
    for (int i = 0; i < 2; i++) {
        const int mrow = row0 + warp_m * 32 + i * 16 + (lane >> 2);
#pragma unroll
        for (int j = 0; j < 4; j++) {
            const int ncol = col0 + warp_n * 32 + j * 8 + ((lane & 3) << 1);
            const float2 bv = *(const float2*)&bias[ncol];
            const float c0 = acc[i][j][0] + bv.x;
            const float c1 = acc[i][j][1] + bv.y;
            const float c2 = acc[i][j][2] + bv.x;
            const float c3 = acc[i][j][3] + bv.y;
            if (SPLIT_OUT) {
                __nv_bfloat162 h0 = __floats2bfloat162_rn(c0, c1);
                float2 hf0 = __bfloat1622float2(h0);
                __nv_bfloat162 l0 = __floats2bfloat162_rn(c0 - hf0.x, c1 - hf0.y);
                __nv_bfloat162 h1 = __floats2bfloat162_rn(c2, c3);
                float2 hf1 = __bfloat1622float2(h1);
                __nv_bfloat162 l1 = __floats2bfloat162_rn(c2 - hf1.x, c3 - hf1.y);
                *(__nv_bfloat162*)&Chi[(size_t)mrow * CDIM + ncol] = h0;
                *(__nv_bfloat162*)&Clo[(size_t)mrow * CDIM + ncol] = l0;
                *(__nv_bfloat162*)&Chi[(size_t)(mrow + 8) * CDIM + ncol] = h1;
                *(__nv_bfloat162*)&Clo[(size_t)(mrow + 8) * CDIM + ncol] = l1;
            } else {
                float2 o0, o1;
                o0.x = c0; o0.y = c1;
                o1.x = c2; o1.y = c3;
                *(float2*)&Cout[(size_t)mrow * CDIM + ncol] = o0;
                *(float2*)&Cout[(size_t)(mrow + 8) * CDIM + ncol] = o1;
            }
        }
    }
}

// ---------------------------------------------------------------------------
// Flash attention (causal) on mma.sync bf16 split.
//   BQ=128 (8 warps x 16 rows), BK=64. 3-stage KV pipeline: the Q smem region
//   is recycled as a third KV buffer after Q fragments are hoisted to regs.
// ---------------------------------------------------------------------------
#define KV_BUF 32768
#define O_KHI 0
#define O_KLO 8192
#define O_VHI 16384
#define O_VLO 24576
#define FA_SMEM (3 * KV_BUF)   // 98304

__global__ __launch_bounds__(256, 1) void flash_attn_mma(
    const __nv_bfloat16* __restrict__ Qhi, const __nv_bfloat16* __restrict__ Qlo,
    const __nv_bfloat16* __restrict__ Khi, const __nv_bfloat16* __restrict__ Klo,
    const __nv_bfloat16* __restrict__ Vhi, const __nv_bfloat16* __restrict__ Vlo,
    __nv_bfloat16* __restrict__ Ohi, __nv_bfloat16* __restrict__ Olo)
{
    extern __shared__ char smem[];
    const uint32_t sbase = smem_to_u32(smem);
    const int tid = threadIdx.x;
    const int lane = tid & 31;
    const int wid = tid >> 5;
    const int qi = (gridDim.x - 1) - blockIdx.x;   // heavy CTAs first
    const int h = blockIdx.y;
    const int b = blockIdx.z;
    const int qrow0 = qi * 128;
    const int m0 = wid * 16;
    const int lr = lane & 7;
    const int lg = lane >> 3;
    const float CS = 0.125f * 1.44269504088896f;   // scale * log2(e)

    // stage buffers: 0 -> +KV_BUF, 1 -> +2*KV_BUF, 2 -> +0 (Q region, recycled)
    const uint32_t kvb0 = sbase + KV_BUF;
    const uint32_t kvb1 = sbase + 2 * KV_BUF;
    const uint32_t kvb2 = sbase;

    // ---- load Q tile into region 0 (128 rows x 64 bf16, hi at +0, lo at +16KB) ----
#pragma unroll
    for (int t = 0; t < 4; t++) {
        const int idx = tid + t * 256;
        const int r = idx >> 3;
        const int c16 = (idx & 7) << 4;
        const uint32_t sw = SWZ128(r * 128 + c16);
        const size_t grow = (size_t)(b * SEQT + qrow0 + r) * CDIM + h * HDIM;
        CP16(sbase + sw, (const char*)(Qhi + grow) + c16);
        CP16(sbase + 16384 + sw, (const char*)(Qlo + grow) + c16);
    }
    CP_COMMIT();

    auto load_kv = [&](int kt, uint32_t sb) {
#pragma unroll
        for (int t = 0; t < 2; t++) {
            const int idx = tid + t * 256;
            const int r = idx >> 3;
            const int c16 = (idx & 7) << 4;
            const uint32_t sw = SWZ128(r * 128 + c16);
            const size_t grow = (size_t)(b * SEQT + kt * 64 + r) * CDIM + h * HDIM;
            CP16(sb + O_KHI + sw, (const char*)(Khi + grow) + c16);
            CP16(sb + O_KLO + sw, (const char*)(Klo + grow) + c16);
            CP16(sb + O_VHI + sw, (const char*)(Vhi + grow) + c16);
            CP16(sb + O_VLO + sw, (const char*)(Vlo + grow) + c16);
        }
        CP_COMMIT();
    };

    const int nkt = 2 * qi + 2;
    load_kv(0, kvb0);
    load_kv(1, kvb1);   // nkt >= 2 always

    // ---- Q landed (kv0/kv1 may still fly); hoist Q fragments to registers ----
    CP_WAIT2();
    __syncthreads();
    uint32_t qfh[4][4], qfl[4][4];
#pragma unroll
    for (int s = 0; s < 4; s++) {
        const uint32_t sw = SWZ128((m0 + ((lg & 1) << 3) + lr) * 128
                                   + s * 32 + ((lg >> 1) << 4));
        ldsm_x4(qfh[s], sbase + sw);
        ldsm_x4(qfl[s], sbase + 16384 + sw);
    }

    float o[8][4];
#pragma unroll
    for (int j = 0; j < 8; j++)
#pragma unroll
        for (int r = 0; r < 4; r++) o[j][r] = 0.0f;
    float mR[2] = {-1e30f, -1e30f};
    float lR[2] = {0.0f, 0.0f};

    for (int kt = 0; kt < nkt; kt++) {
        if (kt + 1 < nkt) { CP_WAIT1(); } else { CP_WAIT0(); }
        __syncthreads();   // all warps done with iter kt-1 (frees buffer (kt+2)%3)
        if (kt + 2 < nkt) {
            const int st = (kt + 2) % 3;
            load_kv(kt + 2, st == 0 ? kvb0 : st == 1 ? kvb1 : kvb2);
        }
        const int cs = kt % 3;
        const uint32_t kb = cs == 0 ? kvb0 : cs == 1 ? kvb1 : kvb2;

        // ---- S = Q @ K^T (split bf16, 3 combos) ----
        float sacc[8][4];
#pragma unroll
        for (int j = 0; j < 8; j++)
#pragma unroll
            for (int r = 0; r < 4; r++) sacc[j][r] = 0.0f;

#pragma unroll
        for (int s = 0; s < 4; s++) {
#pragma unroll
            for (int p = 0; p < 4; p++) {
                const uint32_t sw = SWZ128((p * 16 + ((lg >> 1) << 3) + lr) * 128
                                           + s * 32 + ((lg & 1) << 4));
                uint32_t kh[4], kl[4];
                ldsm_x4(kh, kb + O_KHI + sw);
                ldsm_x4(kl, kb + O_KLO + sw);
                mma16816(sacc[2 * p],     qfh[s], &kh[0]);
                mma16816(sacc[2 * p + 1], qfh[s], &kh[2]);
                mma16816(sacc[2 * p],     qfh[s], &kl[0]);
                mma16816(sacc[2 * p + 1], qfh[s], &kl[2]);
                mma16816(sacc[2 * p],     qfl[s], &kh[0]);
                mma16816(sacc[2 * p + 1], qfl[s], &kh[2]);
            }
        }

        // ---- causal mask ----
        if (kt * 64 + 63 > qrow0 + m0) {
            const int qg0 = qrow0 + m0 + (lane >> 2);
            const int qg1 = qg0 + 8;
#pragma unroll
            for (int j = 0; j < 8; j++) {
                const int kg = kt * 64 + j * 8 + ((lane & 3) << 1);
                if (kg > qg0)     sacc[j][0] = -1e30f;
                if (kg + 1 > qg0) sacc[j][1] = -1e30f;
                if (kg > qg1)     sacc[j][2] = -1e30f;
                if (kg + 1 > qg1) sacc[j][3] = -1e30f;
            }
        }

        // ---- online softmax ----
        float mp0 = sacc[0][0], mp1 = sacc[0][2];
#pragma unroll
        for (int j = 0; j < 8; j++) {
            mp0 = fmaxf(mp0, fmaxf(sacc[j][0], sacc[j][1]));
            mp1 = fmaxf(mp1, fmaxf(sacc[j][2], sacc[j][3]));
        }
        mp0 = fmaxf(mp0, __shfl_xor_sync(0xffffffffu, mp0, 1));
        mp0 = fmaxf(mp0, __shfl_xor_sync(0xffffffffu, mp0, 2));
        mp1 = fmaxf(mp1, __shfl_xor_sync(0xffffffffu, mp1, 1));
        mp1 = fmaxf(mp1, __shfl_xor_sync(0xffffffffu, mp1, 2));
        const float mn0 = fmaxf(mR[0], mp0);
        const float mn1 = fmaxf(mR[1], mp1);
        const float f0 = fast_ex2((mR[0] - mn0) * CS);
        const float f1 = fast_ex2((mR[1] - mn1) * CS);
        float sum0 = 0.0f, sum1 = 0.0f;
#pragma unroll
        for (int j = 0; j < 8; j++) {
            sacc[j][0] = fast_ex2((sacc[j][0] - mn0) * CS);
            sacc[j][1] = fast_ex2((sacc[j][1] - mn0) * CS);
            sacc[j][2] = fast_ex2((sacc[j][2] - mn1) * CS);
            sacc[j][3] = fast_ex2((sacc[j][3] - mn1) * CS);
            sum0 += sacc[j][0] + sacc[j][1];
            sum1 += sacc[j][2] + sacc[j][3];
        }
        sum0 += __shfl_xor_sync(0xffffffffu, sum0, 1);
        sum0 += __shfl_xor_sync(0xffffffffu, sum0, 2);
        sum1 += __shfl_xor_sync(0xffffffffu, sum1, 1);
        sum1 += __shfl_xor_sync(0xffffffffu, sum1, 2);
        lR[0] = lR[0] * f0 + sum0;
        lR[1] = lR[1] * f1 + sum1;
        mR[0] = mn0;
        mR[1] = mn1;
#pragma unroll
        for (int j = 0; j < 8; j++) {
            o[j][0] *= f0; o[j][1] *= f0;
            o[j][2] *= f1; o[j][3] *= f1;
        }

        // ---- O += P @ V (P split in registers, V split from smem) ----
#pragma unroll
        for (int s2 = 0; s2 < 4; s2++) {
            uint32_t ph[4], pl[4];
#pragma unroll
            for (int half = 0; half < 2; half++) {
                const int jt = 2 * s2 + half;
                __nv_bfloat162 h0 = __floats2bfloat162_rn(sacc[jt][0], sacc[jt][1]);
                float2 hf0 = __bfloat1622float2(h0);
                __nv_bfloat162 l0 =
                    __floats2bfloat162_rn(sacc[jt][0] - hf0.x, sacc[jt][1] - hf0.y);
                __nv_bfloat162 h1 = __floats2bfloat162_rn(sacc[jt][2], sacc[jt][3]);
                float2 hf1 = __bfloat1622float2(h1);
                __nv_bfloat162 l1 =
                    __floats2bfloat162_rn(sacc[jt][2] - hf1.x, sacc[jt][3] - hf1.y);
                ph[2 * half]     = *(uint32_t*)&h0;
                ph[2 * half + 1] = *(uint32_t*)&h1;
                pl[2 * half]     = *(uint32_t*)&l0;
                pl[2 * half + 1] = *(uint32_t*)&l1;
            }
#pragma unroll
            for (int dp = 0; dp < 4; dp++) {
                const uint32_t sw = SWZ128((s2 * 16 + ((lg & 1) << 3) + lr) * 128
                                           + dp * 32 + ((lg >> 1) << 4));
                uint32_t vh[4], vl[4];
                ldsm_x4_trans(vh, kb + O_VHI + sw);
                ldsm_x4_trans(vl, kb + O_VLO + sw);
                mma16816(o[2 * dp],     ph, &vh[0]);
                mma16816(o[2 * dp + 1], ph, &vh[2]);
                mma16816(o[2 * dp],     ph, &vl[0]);
                mma16816(o[2 * dp + 1], ph, &vl[2]);
                mma16816(o[2 * dp],     pl, &vh[0]);
                mma16816(o[2 * dp + 1], pl, &vh[2]);
            }
        }
    }

    // ---- normalize + write bf16 hi/lo ----
    const float inv0 = 1.0f / lR[0];
    const float inv1 = 1.0f / lR[1];
    const int r0 = b * SEQT + qrow0 + m0 + (lane >> 2);
#pragma unroll
    for (int j = 0; j < 8; j++) {
        const int col = h * HDIM + j * 8 + ((lane & 3) << 1);
        const float c0 = o[j][0] * inv0, c1 = o[j][1] * inv0;
        const float c2 = o[j][2] * inv1, c3 = o[j][3] * inv1;
        __nv_bfloat162 h0 = __floats2bfloat162_rn(c0, c1);
        float2 hf0 = __bfloat1622float2(h0);
        __nv_bfloat162 l0 = __floats2bfloat162_rn(c0 - hf0.x, c1 - hf0.y);
        __nv_bfloat162 h1 = __floats2bfloat162_rn(c2, c3);
        float2 hf1 = __bfloat1622float2(h1);
        __nv_bfloat162 l1 = __floats2bfloat162_rn(c2 - hf1.x, c3 - hf1.y);
        *(__nv_bfloat162*)&Ohi[(size_t)r0 * CDIM + col] = h0;
        *(__nv_bfloat162*)&Olo[(size_t)r0 * CDIM + col] = l0;
        *(__nv_bfloat162*)&Ohi[(size_t)(r0 + 8) * CDIM + col] = h1;
        *(__nv_bfloat162*)&Olo[(size_t)(r0 + 8) * CDIM + col] = l1;
    }
}

// ---------------------------------------------------------------------------
// Launch
// ---------------------------------------------------------------------------
extern "C" void kernel_launch(void* const* d_in, const int* in_sizes, int n_in,
                              void* d_out, int out_size)
{
    (void)in_sizes; (void)n_in; (void)out_size;
    const float* x  = (const float*)d_in[0];
    const float* Wq = (const float*)d_in[1];
    const float* bq = (const float*)d_in[2];
    const float* Wk = (const float*)d_in[3];
    const float* bk = (const float*)d_in[4];
    const float* Wv = (const float*)d_in[5];
    const float* bv = (const float*)d_in[6];
    const float* Wo = (const float*)d_in[7];
    const float* bo = (const float*)d_in[8];
    float* out = (float*)d_out;

    __nv_bfloat16 *xhi, *xlo, *qhi, *qlo, *khi, *klo, *vhi, *vlo, *ahi, *alo, *wthi, *wtlo;
    cudaGetSymbolAddress((void**)&xhi,  g_xhi);
    cudaGetSymbolAddress((void**)&xlo,  g_xlo);
    cudaGetSymbolAddress((void**)&qhi,  g_qhi);
    cudaGetSymbolAddress((void**)&qlo,  g_qlo);
    cudaGetSymbolAddress((void**)&khi,  g_khi);
    cudaGetSymbolAddress((void**)&klo,  g_klo);
    cudaGetSymbolAddress((void**)&vhi,  g_vhi);
    cudaGetSymbolAddress((void**)&vlo,  g_vlo);
    cudaGetSymbolAddress((void**)&ahi,  g_ahi);
    cudaGetSymbolAddress((void**)&alo,  g_alo);
    cudaGetSymbolAddress((void**)&wthi, g_wthi);
    cudaGetSymbolAddress((void**)&wtlo, g_wtlo);

    cudaFuncSetAttribute(gemm_mma_split<true>,
                         cudaFuncAttributeMaxDynamicSharedMemorySize, GEMM_SMEM);
    cudaFuncSetAttribute(gemm_mma_split<false>,
                         cudaFuncAttributeMaxDynamicSharedMemorySize, GEMM_SMEM);
    cudaFuncSetAttribute(flash_attn_mma,
                         cudaFuncAttributeMaxDynamicSharedMemorySize, FA_SMEM);

    const int nelem = MROWS * CDIM;

    // 1. split x -> bf16 hi/lo
    split_f32<<<(nelem + 255) / 256, 256>>>(x, xhi, xlo, nelem);

    // 2. transpose+split all 4 weights in one launch
    dim3 wt_grid(CDIM / 32, CDIM / 32, 4);
    dim3 wt_blk(32, 8);
    wtrans_split4<<<wt_grid, wt_blk>>>(Wq, Wk, Wv, Wo, wthi, wtlo);

    // 3. fused QKV projection (one launch, 2304 CTAs, 2 CTAs/SM)
    dim3 qkv_grid(36, MROWS / 128);    // (36, 64)
    gemm_mma_split<true><<<qkv_grid, 256, GEMM_SMEM>>>(
        xhi, xlo, wthi, wtlo, bq, bk, bv,
        nullptr, qhi, qlo, khi, klo, vhi, vlo);

    // 4. attention (tensor-core, split bf16) -> bf16 hi/lo
    dim3 fa_grid(SEQT / 128, NHEAD, BATCH);    // (16, 12, 4)
    flash_attn_mma<<<fa_grid, 256, FA_SMEM>>>(qhi, qlo, khi, klo, vhi, vlo, ahi, alo);

    // 5. output projection -> fp32 out
    dim3 wo_grid(12, MROWS / 128);     // (12, 64)
    gemm_mma_split<false><<<wo_grid, 256, GEMM_SMEM>>>(
        ahi, alo, wthi, wtlo, bo, nullptr, nullptr,
        out, nullptr, nullptr, nullptr, nullptr, nullptr, nullptr);
}

// round 7
// speedup vs baseline: 3.9628x; 1.0112x over previous
#include <cuda_runtime.h>
#include <cuda_bf16.h>
#include <math.h>
#include <stdint.h>

#define BATCH 4
#define SEQT 2048
#define CDIM 768
#define NHEAD 12
#define HDIM 64
#define MROWS (BATCH * SEQT)   // 8192

// ---------------------------------------------------------------------------
// Scratch (allocation-free rule: device globals)
// ---------------------------------------------------------------------------
__device__ __nv_bfloat16 g_xhi[(size_t)MROWS * CDIM];
__device__ __nv_bfloat16 g_xlo[(size_t)MROWS * CDIM];
__device__ __nv_bfloat16 g_qhi[(size_t)MROWS * CDIM];
__device__ __nv_bfloat16 g_qlo[(size_t)MROWS * CDIM];
__device__ __nv_bfloat16 g_khi[(size_t)MROWS * CDIM];
__device__ __nv_bfloat16 g_klo[(size_t)MROWS * CDIM];
__device__ __nv_bfloat16 g_vhi[(size_t)MROWS * CDIM];
__device__ __nv_bfloat16 g_vlo[(size_t)MROWS * CDIM];
__device__ __nv_bfloat16 g_ahi[(size_t)MROWS * CDIM];
__device__ __nv_bfloat16 g_alo[(size_t)MROWS * CDIM];
// transposed+split weights: [4][N=CDIM][K=CDIM] (order: Wq, Wk, Wv, Wo)
__device__ __nv_bfloat16 g_wthi[4 * (size_t)CDIM * CDIM];
__device__ __nv_bfloat16 g_wtlo[4 * (size_t)CDIM * CDIM];

// ---------------------------------------------------------------------------
// PTX helpers (sm_80-era: legal under .target sm_103)
// ---------------------------------------------------------------------------
__device__ __forceinline__ uint32_t smem_to_u32(const void* p) {
    uint32_t a;
    asm("{ .reg .u64 t; cvta.to.shared.u64 t, %1; cvt.u32.u64 %0, t; }"
        : "=r"(a) : "l"(p));
    return a;
}

__device__ __forceinline__ void ldsm_x4(uint32_t* r, uint32_t addr) {
    asm volatile("ldmatrix.sync.aligned.m8n8.x4.shared.b16 {%0,%1,%2,%3}, [%4];"
        : "=r"(r[0]), "=r"(r[1]), "=r"(r[2]), "=r"(r[3]) : "r"(addr));
}

__device__ __forceinline__ void ldsm_x4_trans(uint32_t* r, uint32_t addr) {
    asm volatile("ldmatrix.sync.aligned.m8n8.x4.trans.shared.b16 {%0,%1,%2,%3}, [%4];"
        : "=r"(r[0]), "=r"(r[1]), "=r"(r[2]), "=r"(r[3]) : "r"(addr));
}

__device__ __forceinline__ void mma16816(float* c, const uint32_t* a, const uint32_t* b) {
    asm volatile(
        "mma.sync.aligned.m16n8k16.row.col.f32.bf16.bf16.f32 "
        "{%0,%1,%2,%3}, {%4,%5,%6,%7}, {%8,%9}, {%0,%1,%2,%3};"
        : "+f"(c[0]), "+f"(c[1]), "+f"(c[2]), "+f"(c[3])
        : "r"(a[0]), "r"(a[1]), "r"(a[2]), "r"(a[3]), "r"(b[0]), "r"(b[1]));
}

__device__ __forceinline__ float fast_ex2(float x) {
    float y;
    asm("ex2.approx.f32 %0, %1;" : "=f"(y) : "f"(x));
    return y;
}

#define CP16(dst, src) \
    asm volatile("cp.async.cg.shared.global [%0], [%1], 16;" \
                 :: "r"(dst), "l"(src) : "memory")
#define CP_COMMIT() asm volatile("cp.async.commit_group;" ::: "memory")
#define CP_WAIT3()  asm volatile("cp.async.wait_group 3;" ::: "memory")
#define CP_WAIT2()  asm volatile("cp.async.wait_group 2;" ::: "memory")
#define CP_WAIT1()  asm volatile("cp.async.wait_group 1;" ::: "memory")
#define CP_WAIT0()  asm volatile("cp.async.wait_group 0;" ::: "memory")

#define SWZ128(off) ((off) ^ (((off) >> 3) & 0x70))

// 0.125 * log2(e): folded into Q at the QKV GEMM epilogue
#define QK_SCALE 0.18033688011112042f

// ---------------------------------------------------------------------------
// Conversion kernels
// ---------------------------------------------------------------------------
__global__ void split_f32(const float* __restrict__ in,
                          __nv_bfloat16* __restrict__ hi,
                          __nv_bfloat16* __restrict__ lo, int n) {
    int i = blockIdx.x * blockDim.x + threadIdx.x;
    if (i < n) {
        float v = in[i];
        __nv_bfloat16 h = __float2bfloat16(v);
        float r = v - __bfloat162float(h);
        hi[i] = h;
        lo[i] = __float2bfloat16(r);
    }
}

__global__ void wtrans_split4(const float* __restrict__ W0, const float* __restrict__ W1,
                              const float* __restrict__ W2, const float* __restrict__ W3,
                              __nv_bfloat16* __restrict__ hi,
                              __nv_bfloat16* __restrict__ lo) {
    __shared__ float t[32][33];
    const int z = blockIdx.z;
    const float* W = (z == 0) ? W0 : (z == 1) ? W1 : (z == 2) ? W2 : W3;
    const size_t zoff = (size_t)z * CDIM * CDIM;
    const int kx = blockIdx.x * 32;
    const int nx = blockIdx.y * 32;
    const int tx = threadIdx.x, ty = threadIdx.y;
    for (int j = ty; j < 32; j += 8)
        t[j][tx] = W[(size_t)(kx + j) * CDIM + nx + tx];
    __syncthreads();
    for (int j = ty; j < 32; j += 8) {
        float v = t[tx][j];
        __nv_bfloat16 h = __float2bfloat16(v);
        float r = v - __bfloat162float(h);
        size_t o = zoff + (size_t)(nx + j) * CDIM + kx + tx;
        hi[o] = h;
        lo[o] = __float2bfloat16(r);
    }
}

// ---------------------------------------------------------------------------
// mma.sync split-bf16 GEMM, 128x64 tile, 2 stages, 2 CTAs/SM.
// ---------------------------------------------------------------------------
#define GK 64
#define NCHUNK (CDIM / GK)        // 12
#define CH_BYTES 49152
#define GEMM_SMEM (2 * CH_BYTES)  // 98304
#define T_AHI 0
#define T_ALO 16384
#define T_BHI 32768
#define T_BLO 40960

template <bool SPLIT_OUT>
__global__ __launch_bounds__(256, 2) void gemm_mma_split(
    const __nv_bfloat16* __restrict__ Ahi, const __nv_bfloat16* __restrict__ Alo,
    const __nv_bfloat16* __restrict__ Wthi, const __nv_bfloat16* __restrict__ Wtlo,
    const float* __restrict__ b0, const float* __restrict__ b1,
    const float* __restrict__ b2,
    float* __restrict__ Cout,
    __nv_bfloat16* __restrict__ C0hi, __nv_bfloat16* __restrict__ C0lo,
    __nv_bfloat16* __restrict__ C1hi, __nv_bfloat16* __restrict__ C1lo,
    __nv_bfloat16* __restrict__ C2hi, __nv_bfloat16* __restrict__ C2lo)
{
    extern __shared__ char smem[];
    const uint32_t sbase = smem_to_u32(smem);
    const int tid = threadIdx.x;
    const int lane = tid & 31;
    const int wid = tid >> 5;
    const int warp_m = wid >> 1;
    const int warp_n = wid & 1;
    const int row0 = blockIdx.y * 128;

    int wsel, col0;
    if (SPLIT_OUT) { wsel = blockIdx.x / 12; col0 = (blockIdx.x % 12) * 64; }
    else           { wsel = 3;              col0 = blockIdx.x * 64; }

    const size_t WSZ = (size_t)CDIM * CDIM;
    const __nv_bfloat16* Bhi = Wthi + (size_t)wsel * WSZ;
    const __nv_bfloat16* Blo = Wtlo + (size_t)wsel * WSZ;
    const float* bias = SPLIT_OUT ? (wsel == 0 ? b0 : wsel == 1 ? b1 : b2) : b0;
    __nv_bfloat16* Chi = SPLIT_OUT ? (wsel == 0 ? C0hi : wsel == 1 ? C1hi : C2hi) : nullptr;
    __nv_bfloat16* Clo = SPLIT_OUT ? (wsel == 0 ? C0lo : wsel == 1 ? C1lo : C2lo) : nullptr;
    // Q gets pre-scaled by 0.125*log2(e) so flash softmax uses raw ex2
    const float oscale = (SPLIT_OUT && wsel == 0) ? QK_SCALE : 1.0f;

    const int lrow = lane & 7;
    const int lgrp = lane >> 3;
    const int a_roff = ((lgrp & 1) << 3) + lrow;
    const int a_kh   = (lgrp >> 1) << 4;
    const int b_roff = ((lgrp >> 1) << 3) + lrow;
    const int b_kh   = (lgrp & 1) << 4;

    const int ld_r   = tid >> 3;
    const int ld_c16 = (tid & 7) << 4;

    float acc[2][4][4];
#pragma unroll
    for (int i = 0; i < 2; i++)
#pragma unroll
        for (int j = 0; j < 4; j++)
#pragma unroll
            for (int r = 0; r < 4; r++) acc[i][j][r] = 0.0f;

    auto load_chunk = [&](int kc, int stage) {
        const uint32_t sb = sbase + stage * CH_BYTES;
        const int kcol = kc * GK;
#pragma unroll
        for (int t = 0; t < 4; t++) {
            const int r = ld_r + t * 32;
            const uint32_t sw = SWZ128(r * 128 + ld_c16);
            const char* pa  = (const char*)(Ahi + (size_t)(row0 + r) * CDIM + kcol) + ld_c16;
            const char* pal = (const char*)(Alo + (size_t)(row0 + r) * CDIM + kcol) + ld_c16;
            CP16(sb + T_AHI + sw, pa);
            CP16(sb + T_ALO + sw, pal);
        }
#pragma unroll
        for (int t = 0; t < 2; t++) {
            const int idx = tid + t * 256;
            const int r = idx >> 3;
            const int c16 = (idx & 7) << 4;
            const uint32_t sw = SWZ128(r * 128 + c16);
            const char* pb  = (const char*)(Bhi + (size_t)(col0 + r) * CDIM + kcol) + c16;
            const char* pbl = (const char*)(Blo + (size_t)(col0 + r) * CDIM + kcol) + c16;
            CP16(sb + T_BHI + sw, pb);
            CP16(sb + T_BLO + sw, pbl);
        }
        CP_COMMIT();
    };

    load_chunk(0, 0);

    for (int kc = 0; kc < NCHUNK; kc++) {
        CP_WAIT0();
        __syncthreads();
        if (kc + 1 < NCHUNK) load_chunk(kc + 1, (kc + 1) & 1);

        const uint32_t sb = sbase + (kc & 1) * CH_BYTES;
#pragma unroll
        for (int s = 0; s < 4; s++) {
            const int kb = s * 32;
            uint32_t ahi[2][4], alo[2][4];
#pragma unroll
            for (int i = 0; i < 2; i++) {
                const uint32_t off =
                    SWZ128((warp_m * 32 + i * 16 + a_roff) * 128 + kb + a_kh);
                ldsm_x4(ahi[i], sb + T_AHI + off);
                ldsm_x4(alo[i], sb + T_ALO + off);
            }
            uint32_t bhi[4][2], blo[4][2];
#pragma unroll
            for (int j2 = 0; j2 < 2; j2++) {
                const uint32_t off =
                    SWZ128((warp_n * 32 + j2 * 16 + b_roff) * 128 + kb + b_kh);
                uint32_t t[4];
                ldsm_x4(t, sb + T_BHI + off);
                bhi[2 * j2][0] = t[0]; bhi[2 * j2][1] = t[1];
                bhi[2 * j2 + 1][0] = t[2]; bhi[2 * j2 + 1][1] = t[3];
                ldsm_x4(t, sb + T_BLO + off);
                blo[2 * j2][0] = t[0]; blo[2 * j2][1] = t[1];
                blo[2 * j2 + 1][0] = t[2]; blo[2 * j2 + 1][1] = t[3];
            }
#pragma unroll
            for (int i = 0; i < 2; i++)
#pragma unroll
                for (int j = 0; j < 4; j++)
                    mma16816(acc[i][j], ahi[i], bhi[j]);
#pragma unroll
            for (int i = 0; i < 2; i++)
#pragma unroll
                for (int j = 0; j < 4; j++)
                    mma16816(acc[i][j], ahi[i], blo[j]);
#pragma unroll
            for (int i = 0; i < 2; i++)
#pragma unroll
                for (int j = 0; j < 4; j++)
                    mma16816(acc[i][j], alo[i], bhi[j]);
        }
    }

    // ---- epilogue ----
#pragma unroll
    for (int i = 0; i < 2; i++) {
        const int mrow = row0 + warp_m * 32 + i * 16 + (lane >> 2);
#pragma unroll
        for (int j = 0; j < 4; j++) {
            const int ncol = col0 + warp_n * 32 + j * 8 + ((lane & 3) << 1);
            const float2 bv = *(const float2*)&bias[ncol];
            const float c0 = (acc[i][j][0] + bv.x) * oscale;
            const float c1 = (acc[i][j][1] + bv.y) * oscale;
            const float c2 = (acc[i][j][2] + bv.x) * oscale;
            const float c3 = (acc[i][j][3] + bv.y) * oscale;
            if (SPLIT_OUT) {
                __nv_bfloat162 h0 = __floats2bfloat162_rn(c0, c1);
                float2 hf0 = __bfloat1622float2(h0);
                __nv_bfloat162 l0 = __floats2bfloat162_rn(c0 - hf0.x, c1 - hf0.y);
                __nv_bfloat162 h1 = __floats2bfloat162_rn(c2, c3);
                float2 hf1 = __bfloat1622float2(h1);
                __nv_bfloat162 l1 = __floats2bfloat162_rn(c2 - hf1.x, c3 - hf1.y);
                *(__nv_bfloat162*)&Chi[(size_t)mrow * CDIM + ncol] = h0;
                *(__nv_bfloat162*)&Clo[(size_t)mrow * CDIM + ncol] = l0;
                *(__nv_bfloat162*)&Chi[(size_t)(mrow + 8) * CDIM + ncol] = h1;
                *(__nv_bfloat162*)&Clo[(size_t)(mrow + 8) * CDIM + ncol] = l1;
            } else {
                float2 o0, o1;
                o0.x = c0; o0.y = c1;
                o1.x = c2; o1.y = c3;
                *(float2*)&Cout[(size_t)mrow * CDIM + ncol] = o0;
                *(float2*)&Cout[(size_t)(mrow + 8) * CDIM + ncol] = o1;
            }
        }
    }
}

// ---------------------------------------------------------------------------
// Flash attention (causal), software-pipelined:
//   QK(kt+1) MMAs issued BEFORE softmax(kt) so MUFU/ALU softmax overlaps the
//   tensor pipe. 4 KV buffers (prefetch distance 2); Q parked in buffer 3.
//   Q is pre-scaled by 0.125*log2(e) -> softmax uses raw ex2.
// ---------------------------------------------------------------------------
#define KV_BUF 32768
#define O_KHI 0
#define O_KLO 8192
#define O_VHI 16384
#define O_VLO 24576
#define FA_SMEM (4 * KV_BUF)   // 131072

__global__ __launch_bounds__(256, 1) void flash_attn_mma(
    const __nv_bfloat16* __restrict__ Qhi, const __nv_bfloat16* __restrict__ Qlo,
    const __nv_bfloat16* __restrict__ Khi, const __nv_bfloat16* __restrict__ Klo,
    const __nv_bfloat16* __restrict__ Vhi, const __nv_bfloat16* __restrict__ Vlo,
    __nv_bfloat16* __restrict__ Ohi, __nv_bfloat16* __restrict__ Olo)
{
    extern __shared__ char smem[];
    const uint32_t sbase = smem_to_u32(smem);
    const int tid = threadIdx.x;
    const int lane = tid & 31;
    const int wid = tid >> 5;
    const int qi = (gridDim.x - 1) - blockIdx.x;   // heavy CTAs first
    const int h = blockIdx.y;
    const int b = blockIdx.z;
    const int qrow0 = qi * 128;
    const int m0 = wid * 16;
    const int lr = lane & 7;
    const int lg = lane >> 3;

    const int nkt = 2 * qi + 2;   // always even, >= 2

    // ---- load Q into buffer 3 (hi at +0, lo at +16KB) ----
#pragma unroll
    for (int t = 0; t < 4; t++) {
        const int idx = tid + t * 256;
        const int r = idx >> 3;
        const int c16 = (idx & 7) << 4;
        const uint32_t sw = SWZ128(r * 128 + c16);
        const size_t grow = (size_t)(b * SEQT + qrow0 + r) * CDIM + h * HDIM;
        CP16(sbase + 3 * KV_BUF + sw, (const char*)(Qhi + grow) + c16);
        CP16(sbase + 3 * KV_BUF + 16384 + sw, (const char*)(Qlo + grow) + c16);
    }
    CP_COMMIT();

    auto load_kv = [&](int kt) {
        const uint32_t sb = sbase + (uint32_t)(kt & 3) * KV_BUF;
#pragma unroll
        for (int t = 0; t < 2; t++) {
            const int idx = tid + t * 256;
            const int r = idx >> 3;
            const int c16 = (idx & 7) << 4;
            const uint32_t sw = SWZ128(r * 128 + c16);
            const size_t grow = (size_t)(b * SEQT + kt * 64 + r) * CDIM + h * HDIM;
            CP16(sb + O_KHI + sw, (const char*)(Khi + grow) + c16);
            CP16(sb + O_KLO + sw, (const char*)(Klo + grow) + c16);
            CP16(sb + O_VHI + sw, (const char*)(Vhi + grow) + c16);
            CP16(sb + O_VLO + sw, (const char*)(Vlo + grow) + c16);
        }
        CP_COMMIT();
    };

    // kv tiles 0..2 always lie inside this batch's sequence (rows < 192+qrow0... <= SEQT)
    load_kv(0);
    load_kv(1);
    load_kv(2);

    // ---- Q landed; hoist Q fragments to registers ----
    CP_WAIT3();
    __syncthreads();
    uint32_t qfh[4][4], qfl[4][4];
#pragma unroll
    for (int s = 0; s < 4; s++) {
        const uint32_t sw = SWZ128((m0 + ((lg & 1) << 3) + lr) * 128
                                   + s * 32 + ((lg >> 1) << 4));
        ldsm_x4(qfh[s], sbase + 3 * KV_BUF + sw);
        ldsm_x4(qfl[s], sbase + 3 * KV_BUF + 16384 + sw);
    }

    float o[8][4];
#pragma unroll
    for (int j = 0; j < 8; j++)
#pragma unroll
        for (int r = 0; r < 4; r++) o[j][r] = 0.0f;
    float mR[2] = {-1e30f, -1e30f};
    float lR[2] = {0.0f, 0.0f};

    // ---- QK for one tile -> sn ----
    auto qk_tile = [&](int kt, float (&sn)[8][4]) {
        const uint32_t kb = sbase + (uint32_t)(kt & 3) * KV_BUF;
#pragma unroll
        for (int j = 0; j < 8; j++)
#pragma unroll
            for (int r = 0; r < 4; r++) sn[j][r] = 0.0f;
#pragma unroll
        for (int s = 0; s < 4; s++) {
#pragma unroll
            for (int p = 0; p < 4; p++) {
                const uint32_t sw = SWZ128((p * 16 + ((lg >> 1) << 3) + lr) * 128
                                           + s * 32 + ((lg & 1) << 4));
                uint32_t kh[4], kl[4];
                ldsm_x4(kh, kb + O_KHI + sw);
                ldsm_x4(kl, kb + O_KLO + sw);
                mma16816(sn[2 * p],     qfh[s], &kh[0]);
                mma16816(sn[2 * p + 1], qfh[s], &kh[2]);
                mma16816(sn[2 * p],     qfh[s], &kl[0]);
                mma16816(sn[2 * p + 1], qfh[s], &kl[2]);
                mma16816(sn[2 * p],     qfl[s], &kh[0]);
                mma16816(sn[2 * p + 1], qfl[s], &kh[2]);
            }
        }
    };

    // ---- softmax + PV for one tile (scores already in log2e*0.125 units) ----
    auto sm_pv = [&](int kt, float (&sc)[8][4]) {
        if (kt * 64 + 63 > qrow0 + m0) {
            const int qg0 = qrow0 + m0 + (lane >> 2);
            const int qg1 = qg0 + 8;
#pragma unroll
            for (int j = 0; j < 8; j++) {
                const int kg = kt * 64 + j * 8 + ((lane & 3) << 1);
                if (kg > qg0)     sc[j][0] = -1e30f;
                if (kg + 1 > qg0) sc[j][1] = -1e30f;
                if (kg > qg1)     sc[j][2] = -1e30f;
                if (kg + 1 > qg1) sc[j][3] = -1e30f;
            }
        }

        float mp0 = sc[0][0], mp1 = sc[0][2];
#pragma unroll
        for (int j = 0; j < 8; j++) {
            mp0 = fmaxf(mp0, fmaxf(sc[j][0], sc[j][1]));
            mp1 = fmaxf(mp1, fmaxf(sc[j][2], sc[j][3]));
        }
        mp0 = fmaxf(mp0, __shfl_xor_sync(0xffffffffu, mp0, 1));
        mp0 = fmaxf(mp0, __shfl_xor_sync(0xffffffffu, mp0, 2));
        mp1 = fmaxf(mp1, __shfl_xor_sync(0xffffffffu, mp1, 1));
        mp1 = fmaxf(mp1, __shfl_xor_sync(0xffffffffu, mp1, 2));
        const float mn0 = fmaxf(mR[0], mp0);
        const float mn1 = fmaxf(mR[1], mp1);
        const float f0 = fast_ex2(mR[0] - mn0);
        const float f1 = fast_ex2(mR[1] - mn1);
        float sum0 = 0.0f, sum1 = 0.0f;
#pragma unroll
        for (int j = 0; j < 8; j++) {
            sc[j][0] = fast_ex2(sc[j][0] - mn0);
            sc[j][1] = fast_ex2(sc[j][1] - mn0);
            sc[j][2] = fast_ex2(sc[j][2] - mn1);
            sc[j][3] = fast_ex2(sc[j][3] - mn1);
            sum0 += sc[j][0] + sc[j][1];
            sum1 += sc[j][2] + sc[j][3];
        }
        sum0 += __shfl_xor_sync(0xffffffffu, sum0, 1);
        sum0 += __shfl_xor_sync(0xffffffffu, sum0, 2);
        sum1 += __shfl_xor_sync(0xffffffffu, sum1, 1);
        sum1 += __shfl_xor_sync(0xffffffffu, sum1, 2);
        lR[0] = lR[0] * f0 + sum0;
        lR[1] = lR[1] * f1 + sum1;
        mR[0] = mn0;
        mR[1] = mn1;
#pragma unroll
        for (int j = 0; j < 8; j++) {
            o[j][0] *= f0; o[j][1] *= f0;
            o[j][2] *= f1; o[j][3] *= f1;
        }

        const uint32_t kb = sbase + (uint32_t)(kt & 3) * KV_BUF;
#pragma unroll
        for (int s2 = 0; s2 < 4; s2++) {
            uint32_t ph[4], pl[4];
#pragma unroll
            for (int half = 0; half < 2; half++) {
                const int jt = 2 * s2 + half;
                __nv_bfloat162 h0 = __floats2bfloat162_rn(sc[jt][0], sc[jt][1]);
                float2 hf0 = __bfloat1622float2(h0);
                __nv_bfloat162 l0 =
                    __floats2bfloat162_rn(sc[jt][0] - hf0.x, sc[jt][1] - hf0.y);
                __nv_bfloat162 h1 = __floats2bfloat162_rn(sc[jt][2], sc[jt][3]);
                float2 hf1 = __bfloat1622float2(h1);
                __nv_bfloat162 l1 =
                    __floats2bfloat162_rn(sc[jt][2] - hf1.x, sc[jt][3] - hf1.y);
                ph[2 * half]     = *(uint32_t*)&h0;
                ph[2 * half + 1] = *(uint32_t*)&h1;
                pl[2 * half]     = *(uint32_t*)&l0;
                pl[2 * half + 1] = *(uint32_t*)&l1;
            }
#pragma unroll
            for (int dp = 0; dp < 4; dp++) {
                const uint32_t sw = SWZ128((s2 * 16 + ((lg & 1) << 3) + lr) * 128
                                           + dp * 32 + ((lg >> 1) << 4));
                uint32_t vh[4], vl[4];
                ldsm_x4_trans(vh, kb + O_VHI + sw);
                ldsm_x4_trans(vl, kb + O_VLO + sw);
                mma16816(o[2 * dp],     ph, &vh[0]);
                mma16816(o[2 * dp + 1], ph, &vh[2]);
                mma16816(o[2 * dp],     ph, &vl[0]);
                mma16816(o[2 * dp + 1], ph, &vl[2]);
                mma16816(o[2 * dp],     pl, &vh[0]);
                mma16816(o[2 * dp + 1], pl, &vh[2]);
            }
        }
    };

    float sA[8][4], sB[8][4];

    // prologue: kv0 landed (kv1, kv2 may fly) -> S(0)
    CP_WAIT2();
    qk_tile(0, sA);

    // half-step: wait kv(i+1), sync, QK(i+1)->nxt, prefetch kv(i+3), softmax+PV(i)
    auto half_step = [&](int i, float (&cur)[8][4], float (&nxt)[8][4]) {
        if (i + 2 < nkt) { CP_WAIT1(); } else { CP_WAIT0(); }
        __syncthreads();
        if (i + 1 < nkt) qk_tile(i + 1, nxt);
        if (i + 3 < nkt) load_kv(i + 3);
        sm_pv(i, cur);
    };

    for (int kt = 0; kt < nkt; kt += 2) {
        half_step(kt, sA, sB);
        half_step(kt + 1, sB, sA);
    }

    // ---- normalize + write bf16 hi/lo ----
    const float inv0 = 1.0f / lR[0];
    const float inv1 = 1.0f / lR[1];
    const int r0 = b * SEQT + qrow0 + m0 + (lane >> 2);
#pragma unroll
    for (int j = 0; j < 8; j++) {
        const int col = h * HDIM + j * 8 + ((lane & 3) << 1);
        const float c0 = o[j][0] * inv0, c1 = o[j][1] * inv0;
        const float c2 = o[j][2] * inv1, c3 = o[j][3] * inv1;
        __nv_bfloat162 h0 = __floats2bfloat162_rn(c0, c1);
        float2 hf0 = __bfloat1622float2(h0);
        __nv_bfloat162 l0 = __floats2bfloat162_rn(c0 - hf0.x, c1 - hf0.y);
        __nv_bfloat162 h1 = __floats2bfloat162_rn(c2, c3);
        float2 hf1 = __bfloat1622float2(h1);
        __nv_bfloat162 l1 = __floats2bfloat162_rn(c2 - hf1.x, c3 - hf1.y);
        *(__nv_bfloat162*)&Ohi[(size_t)r0 * CDIM + col] = h0;
        *(__nv_bfloat162*)&Olo[(size_t)r0 * CDIM + col] = l0;
        *(__nv_bfloat162*)&Ohi[(size_t)(r0 + 8) * CDIM + col] = h1;
        *(__nv_bfloat162*)&Olo[(size_t)(r0 + 8) * CDIM + col] = l1;
    }
}

// ---------------------------------------------------------------------------
// Launch
// ---------------------------------------------------------------------------
extern "C" void kernel_launch(void* const* d_in, const int* in_sizes, int n_in,
                              void* d_out, int out_size)
{
    (void)in_sizes; (void)n_in; (void)out_size;
    const float* x  = (const float*)d_in[0];
    const float* Wq = (const float*)d_in[1];
    const float* bq = (const float*)d_in[2];
    const float* Wk = (const float*)d_in[3];
    const float* bk = (const float*)d_in[4];
    const float* Wv = (const float*)d_in[5];
    const float* bv = (const float*)d_in[6];
    const float* Wo = (const float*)d_in[7];
    const float* bo = (const float*)d_in[8];
    float* out = (float*)d_out;

    __nv_bfloat16 *xhi, *xlo, *qhi, *qlo, *khi, *klo, *vhi, *vlo, *ahi, *alo, *wthi, *wtlo;
    cudaGetSymbolAddress((void**)&xhi,  g_xhi);
    cudaGetSymbolAddress((void**)&xlo,  g_xlo);
    cudaGetSymbolAddress((void**)&qhi,  g_qhi);
    cudaGetSymbolAddress((void**)&qlo,  g_qlo);
    cudaGetSymbolAddress((void**)&khi,  g_khi);
    cudaGetSymbolAddress((void**)&klo,  g_klo);
    cudaGetSymbolAddress((void**)&vhi,  g_vhi);
    cudaGetSymbolAddress((void**)&vlo,  g_vlo);
    cudaGetSymbolAddress((void**)&ahi,  g_ahi);
    cudaGetSymbolAddress((void**)&alo,  g_alo);
    cudaGetSymbolAddress((void**)&wthi, g_wthi);
    cudaGetSymbolAddress((void**)&wtlo, g_wtlo);

    cudaFuncSetAttribute(gemm_mma_split<true>,
                         cudaFuncAttributeMaxDynamicSharedMemorySize, GEMM_SMEM);
    cudaFuncSetAttribute(gemm_mma_split<false>,
                         cudaFuncAttributeMaxDynamicSharedMemorySize, GEMM_SMEM);
    cudaFuncSetAttribute(flash_attn_mma,
                         cudaFuncAttributeMaxDynamicSharedMemorySize, FA_SMEM);

    const int nelem = MROWS * CDIM;

    split_f32<<<(nelem + 255) / 256, 256>>>(x, xhi, xlo, nelem);

    dim3 wt_grid(CDIM / 32, CDIM / 32, 4);
    dim3 wt_blk(32, 8);
    wtrans_split4<<<wt_grid, wt_blk>>>(Wq, Wk, Wv, Wo, wthi, wtlo);

    dim3 qkv_grid(36, MROWS / 128);
    gemm_mma_split<true><<<qkv_grid, 256, GEMM_SMEM>>>(
        xhi, xlo, wthi, wtlo, bq, bk, bv,
        nullptr, qhi, qlo, khi, klo, vhi, vlo);

    dim3 fa_grid(SEQT / 128, NHEAD, BATCH);
    flash_attn_mma<<<fa_grid, 256, FA_SMEM>>>(qhi, qlo, khi, klo, vhi, vlo, ahi, alo);

    dim3 wo_grid(12, MROWS / 128);
    gemm_mma_split<false><<<wo_grid, 256, GEMM_SMEM>>>(
        ahi, alo, wthi, wtlo, bo, nullptr, nullptr,
        out, nullptr, nullptr, nullptr, nullptr, nullptr, nullptr);
}

// round 8
// speedup vs baseline: 4.1421x; 1.0452x over previous
#include <cuda_runtime.h>
#include <cuda_bf16.h>
#include <math.h>
#include <stdint.h>

#define BATCH 4
#define SEQT 2048
#define CDIM 768
#define NHEAD 12
#define HDIM 64
#define MROWS (BATCH * SEQT)   // 8192

// ---------------------------------------------------------------------------
// Scratch (allocation-free rule: device globals)
// ---------------------------------------------------------------------------
__device__ __nv_bfloat16 g_xhi[(size_t)MROWS * CDIM];
__device__ __nv_bfloat16 g_xlo[(size_t)MROWS * CDIM];
__device__ __nv_bfloat16 g_qhi[(size_t)MROWS * CDIM];
__device__ __nv_bfloat16 g_qlo[(size_t)MROWS * CDIM];
__device__ __nv_bfloat16 g_khi[(size_t)MROWS * CDIM];
__device__ __nv_bfloat16 g_klo[(size_t)MROWS * CDIM];
__device__ __nv_bfloat16 g_vhi[(size_t)MROWS * CDIM];
__device__ __nv_bfloat16 g_vlo[(size_t)MROWS * CDIM];
__device__ __nv_bfloat16 g_ahi[(size_t)MROWS * CDIM];
__device__ __nv_bfloat16 g_alo[(size_t)MROWS * CDIM];
// transposed+split weights: [4][N=CDIM][K=CDIM] (order: Wq, Wk, Wv, Wo)
__device__ __nv_bfloat16 g_wthi[4 * (size_t)CDIM * CDIM];
__device__ __nv_bfloat16 g_wtlo[4 * (size_t)CDIM * CDIM];

// ---------------------------------------------------------------------------
// PTX helpers (sm_80-era: legal under .target sm_103)
// ---------------------------------------------------------------------------
__device__ __forceinline__ uint32_t smem_to_u32(const void* p) {
    uint32_t a;
    asm("{ .reg .u64 t; cvta.to.shared.u64 t, %1; cvt.u32.u64 %0, t; }"
        : "=r"(a) : "l"(p));
    return a;
}

__device__ __forceinline__ void ldsm_x4(uint32_t* r, uint32_t addr) {
    asm volatile("ldmatrix.sync.aligned.m8n8.x4.shared.b16 {%0,%1,%2,%3}, [%4];"
        : "=r"(r[0]), "=r"(r[1]), "=r"(r[2]), "=r"(r[3]) : "r"(addr));
}

__device__ __forceinline__ void ldsm_x4_trans(uint32_t* r, uint32_t addr) {
    asm volatile("ldmatrix.sync.aligned.m8n8.x4.trans.shared.b16 {%0,%1,%2,%3}, [%4];"
        : "=r"(r[0]), "=r"(r[1]), "=r"(r[2]), "=r"(r[3]) : "r"(addr));
}

__device__ __forceinline__ void mma16816(float* c, const uint32_t* a, const uint32_t* b) {
    asm volatile(
        "mma.sync.aligned.m16n8k16.row.col.f32.bf16.bf16.f32 "
        "{%0,%1,%2,%3}, {%4,%5,%6,%7}, {%8,%9}, {%0,%1,%2,%3};"
        : "+f"(c[0]), "+f"(c[1]), "+f"(c[2]), "+f"(c[3])
        : "r"(a[0]), "r"(a[1]), "r"(a[2]), "r"(a[3]), "r"(b[0]), "r"(b[1]));
}

__device__ __forceinline__ float fast_ex2(float x) {
    float y;
    asm("ex2.approx.f32 %0, %1;" : "=f"(y) : "f"(x));
    return y;
}

#define CP16(dst, src) \
    asm volatile("cp.async.cg.shared.global [%0], [%1], 16;" \
                 :: "r"(dst), "l"(src) : "memory")
#define CP_COMMIT() asm volatile("cp.async.commit_group;" ::: "memory")
#define CP_WAIT1()  asm volatile("cp.async.wait_group 1;" ::: "memory")
#define CP_WAIT0()  asm volatile("cp.async.wait_group 0;" ::: "memory")

#define SWZ128(off) ((off) ^ (((off) >> 3) & 0x70))

// 0.125 * log2(e): folded into Q at the QKV GEMM epilogue
#define QK_SCALE 0.18033688011112042f

// ---------------------------------------------------------------------------
// Conversion kernels
// ---------------------------------------------------------------------------
__global__ void split_f32(const float* __restrict__ in,
                          __nv_bfloat16* __restrict__ hi,
                          __nv_bfloat16* __restrict__ lo, int n) {
    int i = blockIdx.x * blockDim.x + threadIdx.x;
    if (i < n) {
        float v = in[i];
        __nv_bfloat16 h = __float2bfloat16(v);
        float r = v - __bfloat162float(h);
        hi[i] = h;
        lo[i] = __float2bfloat16(r);
    }
}

__global__ void wtrans_split4(const float* __restrict__ W0, const float* __restrict__ W1,
                              const float* __restrict__ W2, const float* __restrict__ W3,
                              __nv_bfloat16* __restrict__ hi,
                              __nv_bfloat16* __restrict__ lo) {
    __shared__ float t[32][33];
    const int z = blockIdx.z;
    const float* W = (z == 0) ? W0 : (z == 1) ? W1 : (z == 2) ? W2 : W3;
    const size_t zoff = (size_t)z * CDIM * CDIM;
    const int kx = blockIdx.x * 32;
    const int nx = blockIdx.y * 32;
    const int tx = threadIdx.x, ty = threadIdx.y;
    for (int j = ty; j < 32; j += 8)
        t[j][tx] = W[(size_t)(kx + j) * CDIM + nx + tx];
    __syncthreads();
    for (int j = ty; j < 32; j += 8) {
        float v = t[tx][j];
        __nv_bfloat16 h = __float2bfloat16(v);
        float r = v - __bfloat162float(h);
        size_t o = zoff + (size_t)(nx + j) * CDIM + kx + tx;
        hi[o] = h;
        lo[o] = __float2bfloat16(r);
    }
}

// ---------------------------------------------------------------------------
// mma.sync split-bf16 GEMM, 128x64 tile, 2 stages, 2 CTAs/SM. (unchanged)
// ---------------------------------------------------------------------------
#define GK 64
#define NCHUNK (CDIM / GK)        // 12
#define CH_BYTES 49152
#define GEMM_SMEM (2 * CH_BYTES)  // 98304
#define T_AHI 0
#define T_ALO 16384
#define T_BHI 32768
#define T_BLO 40960

template <bool SPLIT_OUT>
__global__ __launch_bounds__(256, 2) void gemm_mma_split(
    const __nv_bfloat16* __restrict__ Ahi, const __nv_bfloat16* __restrict__ Alo,
    const __nv_bfloat16* __restrict__ Wthi, const __nv_bfloat16* __restrict__ Wtlo,
    const float* __restrict__ b0, const float* __restrict__ b1,
    const float* __restrict__ b2,
    float* __restrict__ Cout,
    __nv_bfloat16* __restrict__ C0hi, __nv_bfloat16* __restrict__ C0lo,
    __nv_bfloat16* __restrict__ C1hi, __nv_bfloat16* __restrict__ C1lo,
    __nv_bfloat16* __restrict__ C2hi, __nv_bfloat16* __restrict__ C2lo)
{
    extern __shared__ char smem[];
    const uint32_t sbase = smem_to_u32(smem);
    const int tid = threadIdx.x;
    const int lane = tid & 31;
    const int wid = tid >> 5;
    const int warp_m = wid >> 1;
    const int warp_n = wid & 1;
    const int row0 = blockIdx.y * 128;

    int wsel, col0;
    if (SPLIT_OUT) { wsel = blockIdx.x / 12; col0 = (blockIdx.x % 12) * 64; }
    else           { wsel = 3;              col0 = blockIdx.x * 64; }

    const size_t WSZ = (size_t)CDIM * CDIM;
    const __nv_bfloat16* Bhi = Wthi + (size_t)wsel * WSZ;
    const __nv_bfloat16* Blo = Wtlo + (size_t)wsel * WSZ;
    const float* bias = SPLIT_OUT ? (wsel == 0 ? b0 : wsel == 1 ? b1 : b2) : b0;
    __nv_bfloat16* Chi = SPLIT_OUT ? (wsel == 0 ? C0hi : wsel == 1 ? C1hi : C2hi) : nullptr;
    __nv_bfloat16* Clo = SPLIT_OUT ? (wsel == 0 ? C0lo : wsel == 1 ? C1lo : C2lo) : nullptr;
    const float oscale = (SPLIT_OUT && wsel == 0) ? QK_SCALE : 1.0f;

    const int lrow = lane & 7;
    const int lgrp = lane >> 3;
    const int a_roff = ((lgrp & 1) << 3) + lrow;
    const int a_kh   = (lgrp >> 1) << 4;
    const int b_roff = ((lgrp >> 1) << 3) + lrow;
    const int b_kh   = (lgrp & 1) << 4;

    const int ld_r   = tid >> 3;
    const int ld_c16 = (tid & 7) << 4;

    float acc[2][4][4];
#pragma unroll
    for (int i = 0; i < 2; i++)
#pragma unroll
        for (int j = 0; j < 4; j++)
#pragma unroll
            for (int r = 0; r < 4; r++) acc[i][j][r] = 0.0f;

    auto load_chunk = [&](int kc, int stage) {
        const uint32_t sb = sbase + stage * CH_BYTES;
        const int kcol = kc * GK;
#pragma unroll
        for (int t = 0; t < 4; t++) {
            const int r = ld_r + t * 32;
            const uint32_t sw = SWZ128(r * 128 + ld_c16);
            const char* pa  = (const char*)(Ahi + (size_t)(row0 + r) * CDIM + kcol) + ld_c16;
            const char* pal = (const char*)(Alo + (size_t)(row0 + r) * CDIM + kcol) + ld_c16;
            CP16(sb + T_AHI + sw, pa);
            CP16(sb + T_ALO + sw, pal);
        }
#pragma unroll
        for (int t = 0; t < 2; t++) {
            const int idx = tid + t * 256;
            const int r = idx >> 3;
            const int c16 = (idx & 7) << 4;
            const uint32_t sw = SWZ128(r * 128 + c16);
            const char* pb  = (const char*)(Bhi + (size_t)(col0 + r) * CDIM + kcol) + c16;
            const char* pbl = (const char*)(Blo + (size_t)(col0 + r) * CDIM + kcol) + c16;
            CP16(sb + T_BHI + sw, pb);
            CP16(sb + T_BLO + sw, pbl);
        }
        CP_COMMIT();
    };

    load_chunk(0, 0);

    for (int kc = 0; kc < NCHUNK; kc++) {
        CP_WAIT0();
        __syncthreads();
        if (kc + 1 < NCHUNK) load_chunk(kc + 1, (kc + 1) & 1);

        const uint32_t sb = sbase + (kc & 1) * CH_BYTES;
#pragma unroll
        for (int s = 0; s < 4; s++) {
            const int kb = s * 32;
            uint32_t ahi[2][4], alo[2][4];
#pragma unroll
            for (int i = 0; i < 2; i++) {
                const uint32_t off =
                    SWZ128((warp_m * 32 + i * 16 + a_roff) * 128 + kb + a_kh);
                ldsm_x4(ahi[i], sb + T_AHI + off);
                ldsm_x4(alo[i], sb + T_ALO + off);
            }
            uint32_t bhi[4][2], blo[4][2];
#pragma unroll
            for (int j2 = 0; j2 < 2; j2++) {
                const uint32_t off =
                    SWZ128((warp_n * 32 + j2 * 16 + b_roff) * 128 + kb + b_kh);
                uint32_t t[4];
                ldsm_x4(t, sb + T_BHI + off);
                bhi[2 * j2][0] = t[0]; bhi[2 * j2][1] = t[1];
                bhi[2 * j2 + 1][0] = t[2]; bhi[2 * j2 + 1][1] = t[3];
                ldsm_x4(t, sb + T_BLO + off);
                blo[2 * j2][0] = t[0]; blo[2 * j2][1] = t[1];
                blo[2 * j2 + 1][0] = t[2]; blo[2 * j2 + 1][1] = t[3];
            }
#pragma unroll
            for (int i = 0; i < 2; i++)
#pragma unroll
                for (int j = 0; j < 4; j++)
                    mma16816(acc[i][j], ahi[i], bhi[j]);
#pragma unroll
            for (int i = 0; i < 2; i++)
#pragma unroll
                for (int j = 0; j < 4; j++)
                    mma16816(acc[i][j], ahi[i], blo[j]);
#pragma unroll
            for (int i = 0; i < 2; i++)
#pragma unroll
                for (int j = 0; j < 4; j++)
                    mma16816(acc[i][j], alo[i], bhi[j]);
        }
    }

    // ---- epilogue ----
#pragma unroll
    for (int i = 0; i < 2; i++) {
        const int mrow = row0 + warp_m * 32 + i * 16 + (lane >> 2);
#pragma unroll
        for (int j = 0; j < 4; j++) {
            const int ncol = col0 + warp_n * 32 + j * 8 + ((lane & 3) << 1);
            const float2 bv = *(const float2*)&bias[ncol];
            const float c0 = (acc[i][j][0] + bv.x) * oscale;
            const float c1 = (acc[i][j][1] + bv.y) * oscale;
            const float c2 = (acc[i][j][2] + bv.x) * oscale;
            const float c3 = (acc[i][j][3] + bv.y) * oscale;
            if (SPLIT_OUT) {
                __nv_bfloat162 h0 = __floats2bfloat162_rn(c0, c1);
                float2 hf0 = __bfloat1622float2(h0);
                __nv_bfloat162 l0 = __floats2bfloat162_rn(c0 - hf0.x, c1 - hf0.y);
                __nv_bfloat162 h1 = __floats2bfloat162_rn(c2, c3);
                float2 hf1 = __bfloat1622float2(h1);
                __nv_bfloat162 l1 = __floats2bfloat162_rn(c2 - hf1.x, c3 - hf1.y);
                *(__nv_bfloat162*)&Chi[(size_t)mrow * CDIM + ncol] = h0;
                *(__nv_bfloat162*)&Clo[(size_t)mrow * CDIM + ncol] = l0;
                *(__nv_bfloat162*)&Chi[(size_t)(mrow + 8) * CDIM + ncol] = h1;
                *(__nv_bfloat162*)&Clo[(size_t)(mrow + 8) * CDIM + ncol] = l1;
            } else {
                float2 o0, o1;
                o0.x = c0; o0.y = c1;
                o1.x = c2; o1.y = c3;
                *(float2*)&Cout[(size_t)mrow * CDIM + ncol] = o0;
                *(float2*)&Cout[(size_t)(mrow + 8) * CDIM + ncol] = o1;
            }
        }
    }
}

// ---------------------------------------------------------------------------
// Flash attention (causal): 128 threads (4 warps), BQ=64, 2 CTAs/SM.
//   Cross-CTA overlap: one CTA's softmax fills the other's tensor-pipe gaps.
//   2 KV buffers (64KB) + Q region (16KB) = 80KB/CTA.
//   Strict wait -> syncthreads -> compute ordering (no cp.async races).
//   Q pre-scaled by 0.125*log2(e) -> softmax uses raw ex2.
// ---------------------------------------------------------------------------
#define KV_BUF 32768
#define O_KHI 0
#define O_KLO 8192
#define O_VHI 16384
#define O_VLO 24576
#define Q_OFF (2 * KV_BUF)
#define FA_SMEM (2 * KV_BUF + 16384)   // 81920

__global__ __launch_bounds__(128, 2) void flash_attn_mma(
    const __nv_bfloat16* __restrict__ Qhi, const __nv_bfloat16* __restrict__ Qlo,
    const __nv_bfloat16* __restrict__ Khi, const __nv_bfloat16* __restrict__ Klo,
    const __nv_bfloat16* __restrict__ Vhi, const __nv_bfloat16* __restrict__ Vlo,
    __nv_bfloat16* __restrict__ Ohi, __nv_bfloat16* __restrict__ Olo)
{
    extern __shared__ char smem[];
    const uint32_t sbase = smem_to_u32(smem);
    const int tid = threadIdx.x;
    const int lane = tid & 31;
    const int wid = tid >> 5;                      // 0..3
    const int qi = (gridDim.x - 1) - blockIdx.x;   // heavy CTAs first
    const int h = blockIdx.y;
    const int b = blockIdx.z;
    const int qrow0 = qi * 64;
    const int m0 = wid * 16;
    const int lr = lane & 7;
    const int lg = lane >> 3;

    const int nkt = qi + 1;

    // ---- load Q tile (64 rows; hi at Q_OFF, lo at Q_OFF+8KB) ----
#pragma unroll
    for (int t = 0; t < 4; t++) {
        const int idx = tid + t * 128;             // 0..511
        const int r = idx >> 3;
        const int c16 = (idx & 7) << 4;
        const uint32_t sw = SWZ128(r * 128 + c16);
        const size_t grow = (size_t)(b * SEQT + qrow0 + r) * CDIM + h * HDIM;
        CP16(sbase + Q_OFF + sw, (const char*)(Qhi + grow) + c16);
        CP16(sbase + Q_OFF + 8192 + sw, (const char*)(Qlo + grow) + c16);
    }
    CP_COMMIT();

    auto load_kv = [&](int kt) {
        const uint32_t sb = sbase + (uint32_t)(kt & 1) * KV_BUF;
#pragma unroll
        for (int t = 0; t < 4; t++) {
            const int idx = tid + t * 128;         // 0..511
            const int r = idx >> 3;
            const int c16 = (idx & 7) << 4;
            const uint32_t sw = SWZ128(r * 128 + c16);
            const size_t grow = (size_t)(b * SEQT + kt * 64 + r) * CDIM + h * HDIM;
            CP16(sb + O_KHI + sw, (const char*)(Khi + grow) + c16);
            CP16(sb + O_KLO + sw, (const char*)(Klo + grow) + c16);
            CP16(sb + O_VHI + sw, (const char*)(Vhi + grow) + c16);
            CP16(sb + O_VLO + sw, (const char*)(Vlo + grow) + c16);
        }
        CP_COMMIT();
    };
    load_kv(0);

    // ---- Q landed for all threads; hoist Q fragments to registers ----
    CP_WAIT1();
    __syncthreads();
    uint32_t qfh[4][4], qfl[4][4];
#pragma unroll
    for (int s = 0; s < 4; s++) {
        const uint32_t sw = SWZ128((m0 + ((lg & 1) << 3) + lr) * 128
                                   + s * 32 + ((lg >> 1) << 4));
        ldsm_x4(qfh[s], sbase + Q_OFF + sw);
        ldsm_x4(qfl[s], sbase + Q_OFF + 8192 + sw);
    }

    float o[8][4];
#pragma unroll
    for (int j = 0; j < 8; j++)
#pragma unroll
        for (int r = 0; r < 4; r++) o[j][r] = 0.0f;
    float mR[2] = {-1e30f, -1e30f};
    float lR[2] = {0.0f, 0.0f};

    for (int kt = 0; kt < nkt; kt++) {
        CP_WAIT0();        // kv(kt) landed (this thread's groups all retired)
        __syncthreads();   // everyone's writes visible; prev-iter reads done
        if (kt + 1 < nkt) load_kv(kt + 1);
        const uint32_t kb = sbase + (uint32_t)(kt & 1) * KV_BUF;

        // ---- S = Q @ K^T (split bf16, 3 combos) ----
        float sacc[8][4];
#pragma unroll
        for (int j = 0; j < 8; j++)
#pragma unroll
            for (int r = 0; r < 4; r++) sacc[j][r] = 0.0f;

#pragma unroll
        for (int s = 0; s < 4; s++) {
#pragma unroll
            for (int p = 0; p < 4; p++) {
                const uint32_t sw = SWZ128((p * 16 + ((lg >> 1) << 3) + lr) * 128
                                           + s * 32 + ((lg & 1) << 4));
                uint32_t kh[4], kl[4];
                ldsm_x4(kh, kb + O_KHI + sw);
                ldsm_x4(kl, kb + O_KLO + sw);
                mma16816(sacc[2 * p],     qfh[s], &kh[0]);
                mma16816(sacc[2 * p + 1], qfh[s], &kh[2]);
                mma16816(sacc[2 * p],     qfh[s], &kl[0]);
                mma16816(sacc[2 * p + 1], qfh[s], &kl[2]);
                mma16816(sacc[2 * p],     qfl[s], &kh[0]);
                mma16816(sacc[2 * p + 1], qfl[s], &kh[2]);
            }
        }

        // ---- causal mask (only the diagonal tile kt == qi) ----
        if (kt == nkt - 1) {
            const int qg0 = qrow0 + m0 + (lane >> 2);
            const int qg1 = qg0 + 8;
#pragma unroll
            for (int j = 0; j < 8; j++) {
                const int kg = kt * 64 + j * 8 + ((lane & 3) << 1);
                if (kg > qg0)     sacc[j][0] = -1e30f;
                if (kg + 1 > qg0) sacc[j][1] = -1e30f;
                if (kg > qg1)     sacc[j][2] = -1e30f;
                if (kg + 1 > qg1) sacc[j][3] = -1e30f;
            }
        }

        // ---- online softmax (scores already in log2 units) ----
        float mp0 = sacc[0][0], mp1 = sacc[0][2];
#pragma unroll
        for (int j = 0; j < 8; j++) {
            mp0 = fmaxf(mp0, fmaxf(sacc[j][0], sacc[j][1]));
            mp1 = fmaxf(mp1, fmaxf(sacc[j][2], sacc[j][3]));
        }
        mp0 = fmaxf(mp0, __shfl_xor_sync(0xffffffffu, mp0, 1));
        mp0 = fmaxf(mp0, __shfl_xor_sync(0xffffffffu, mp0, 2));
        mp1 = fmaxf(mp1, __shfl_xor_sync(0xffffffffu, mp1, 1));
        mp1 = fmaxf(mp1, __shfl_xor_sync(0xffffffffu, mp1, 2));
        const float mn0 = fmaxf(mR[0], mp0);
        const float mn1 = fmaxf(mR[1], mp1);
        const float f0 = fast_ex2(mR[0] - mn0);
        const float f1 = fast_ex2(mR[1] - mn1);
        float sum0 = 0.0f, sum1 = 0.0f;
#pragma unroll
        for (int j = 0; j < 8; j++) {
            sacc[j][0] = fast_ex2(sacc[j][0] - mn0);
            sacc[j][1] = fast_ex2(sacc[j][1] - mn0);
            sacc[j][2] = fast_ex2(sacc[j][2] - mn1);
            sacc[j][3] = fast_ex2(sacc[j][3] - mn1);
            sum0 += sacc[j][0] + sacc[j][1];
            sum1 += sacc[j][2] + sacc[j][3];
        }
        sum0 += __shfl_xor_sync(0xffffffffu, sum0, 1);
        sum0 += __shfl_xor_sync(0xffffffffu, sum0, 2);
        sum1 += __shfl_xor_sync(0xffffffffu, sum1, 1);
        sum1 += __shfl_xor_sync(0xffffffffu, sum1, 2);
        lR[0] = lR[0] * f0 + sum0;
        lR[1] = lR[1] * f1 + sum1;
        mR[0] = mn0;
        mR[1] = mn1;
#pragma unroll
        for (int j = 0; j < 8; j++) {
            o[j][0] *= f0; o[j][1] *= f0;
            o[j][2] *= f1; o[j][3] *= f1;
        }

        // ---- O += P @ V (P split in registers, V split from smem) ----
#pragma unroll
        for (int s2 = 0; s2 < 4; s2++) {
            uint32_t ph[4], pl[4];
#pragma unroll
            for (int half = 0; half < 2; half++) {
                const int jt = 2 * s2 + half;
                __nv_bfloat162 h0 = __floats2bfloat162_rn(sacc[jt][0], sacc[jt][1]);
                float2 hf0 = __bfloat1622float2(h0);
                __nv_bfloat162 l0 =
                    __floats2bfloat162_rn(sacc[jt][0] - hf0.x, sacc[jt][1] - hf0.y);
                __nv_bfloat162 h1 = __floats2bfloat162_rn(sacc[jt][2], sacc[jt][3]);
                float2 hf1 = __bfloat1622float2(h1);
                __nv_bfloat162 l1 =
                    __floats2bfloat162_rn(sacc[jt][2] - hf1.x, sacc[jt][3] - hf1.y);
                ph[2 * half]     = *(uint32_t*)&h0;
                ph[2 * half + 1] = *(uint32_t*)&h1;
                pl[2 * half]     = *(uint32_t*)&l0;
                pl[2 * half + 1] = *(uint32_t*)&l1;
            }
#pragma unroll
            for (int dp = 0; dp < 4; dp++) {
                const uint32_t sw = SWZ128((s2 * 16 + ((lg & 1) << 3) + lr) * 128
                                           + dp * 32 + ((lg >> 1) << 4));
                uint32_t vh[4], vl[4];
                ldsm_x4_trans(vh, kb + O_VHI + sw);
                ldsm_x4_trans(vl, kb + O_VLO + sw);
                mma16816(o[2 * dp],     ph, &vh[0]);
                mma16816(o[2 * dp + 1], ph, &vh[2]);
                mma16816(o[2 * dp],     ph, &vl[0]);
                mma16816(o[2 * dp + 1], ph, &vl[2]);
                mma16816(o[2 * dp],     pl, &vh[0]);
                mma16816(o[2 * dp + 1], pl, &vh[2]);
            }
        }
    }

    // ---- normalize + write bf16 hi/lo ----
    const float inv0 = 1.0f / lR[0];
    const float inv1 = 1.0f / lR[1];
    const int r0 = b * SEQT + qrow0 + m0 + (lane >> 2);
#pragma unroll
    for (int j = 0; j < 8; j++) {
        const int col = h * HDIM + j * 8 + ((lane & 3) << 1);
        const float c0 = o[j][0] * inv0, c1 = o[j][1] * inv0;
        const float c2 = o[j][2] * inv1, c3 = o[j][3] * inv1;
        __nv_bfloat162 h0 = __floats2bfloat162_rn(c0, c1);
        float2 hf0 = __bfloat1622float2(h0);
        __nv_bfloat162 l0 = __floats2bfloat162_rn(c0 - hf0.x, c1 - hf0.y);
        __nv_bfloat162 h1 = __floats2bfloat162_rn(c2, c3);
        float2 hf1 = __bfloat1622float2(h1);
        __nv_bfloat162 l1 = __floats2bfloat162_rn(c2 - hf1.x, c3 - hf1.y);
        *(__nv_bfloat162*)&Ohi[(size_t)r0 * CDIM + col] = h0;
        *(__nv_bfloat162*)&Olo[(size_t)r0 * CDIM + col] = l0;
        *(__nv_bfloat162*)&Ohi[(size_t)(r0 + 8) * CDIM + col] = h1;
        *(__nv_bfloat162*)&Olo[(size_t)(r0 + 8) * CDIM + col] = l1;
    }
}

// ---------------------------------------------------------------------------
// Launch
// ---------------------------------------------------------------------------
extern "C" void kernel_launch(void* const* d_in, const int* in_sizes, int n_in,
                              void* d_out, int out_size)
{
    (void)in_sizes; (void)n_in; (void)out_size;
    const float* x  = (const float*)d_in[0];
    const float* Wq = (const float*)d_in[1];
    const float* bq = (const float*)d_in[2];
    const float* Wk = (const float*)d_in[3];
    const float* bk = (const float*)d_in[4];
    const float* Wv = (const float*)d_in[5];
    const float* bv = (const float*)d_in[6];
    const float* Wo = (const float*)d_in[7];
    const float* bo = (const float*)d_in[8];
    float* out = (float*)d_out;

    __nv_bfloat16 *xhi, *xlo, *qhi, *qlo, *khi, *klo, *vhi, *vlo, *ahi, *alo, *wthi, *wtlo;
    cudaGetSymbolAddress((void**)&xhi,  g_xhi);
    cudaGetSymbolAddress((void**)&xlo,  g_xlo);
    cudaGetSymbolAddress((void**)&qhi,  g_qhi);
    cudaGetSymbolAddress((void**)&qlo,  g_qlo);
    cudaGetSymbolAddress((void**)&khi,  g_khi);
    cudaGetSymbolAddress((void**)&klo,  g_klo);
    cudaGetSymbolAddress((void**)&vhi,  g_vhi);
    cudaGetSymbolAddress((void**)&vlo,  g_vlo);
    cudaGetSymbolAddress((void**)&ahi,  g_ahi);
    cudaGetSymbolAddress((void**)&alo,  g_alo);
    cudaGetSymbolAddress((void**)&wthi, g_wthi);
    cudaGetSymbolAddress((void**)&wtlo, g_wtlo);

    cudaFuncSetAttribute(gemm_mma_split<true>,
                         cudaFuncAttributeMaxDynamicSharedMemorySize, GEMM_SMEM);
    cudaFuncSetAttribute(gemm_mma_split<false>,
                         cudaFuncAttributeMaxDynamicSharedMemorySize, GEMM_SMEM);
    cudaFuncSetAttribute(flash_attn_mma,
                         cudaFuncAttributeMaxDynamicSharedMemorySize, FA_SMEM);

    const int nelem = MROWS * CDIM;

    split_f32<<<(nelem + 255) / 256, 256>>>(x, xhi, xlo, nelem);

    dim3 wt_grid(CDIM / 32, CDIM / 32, 4);
    dim3 wt_blk(32, 8);
    wtrans_split4<<<wt_grid, wt_blk>>>(Wq, Wk, Wv, Wo, wthi, wtlo);

    dim3 qkv_grid(36, MROWS / 128);
    gemm_mma_split<true><<<qkv_grid, 256, GEMM_SMEM>>>(
        xhi, xlo, wthi, wtlo, bq, bk, bv,
        nullptr, qhi, qlo, khi, klo, vhi, vlo);

    dim3 fa_grid(SEQT / 64, NHEAD, BATCH);     // (32, 12, 4) = 1536 CTAs
    flash_attn_mma<<<fa_grid, 128, FA_SMEM>>>(qhi, qlo, khi, klo, vhi, vlo, ahi, alo);

    dim3 wo_grid(12, MROWS / 128);
    gemm_mma_split<false><<<wo_grid, 256, GEMM_SMEM>>>(
        ahi, alo, wthi, wtlo, bo, nullptr, nullptr,
        out, nullptr, nullptr, nullptr, nullptr, nullptr, nullptr);
}